// round 1
// baseline (speedup 1.0000x reference)
#include <cuda_runtime.h>
#include <cstddef>

#define NUMNODES 32768
#define NCHAIN   1024

// -------- global scratch (no allocations allowed) --------
__device__ float g_msg[(size_t)NUMNODES * 1024];   // 128 MB message buffer
__device__ float g_alpha[(size_t)NUMNODES * 16];   // attention logits per (node, head)
__device__ float g_bufA[(size_t)NUMNODES * 128];   // activation double buffer
__device__ float g_bufB[(size_t)NUMNODES * 128];

// ============================================================
// Phase A (layers 1-4, HC = H*C = 1024):
// msg[g] = leaky_relu(x[g] @ Wm + bm); alpha[g,h] = <msg[g,h,:], att[h,:]>
// 8 nodes per block, 256 threads, 4 outputs per thread:
// 32 FMA per Wm load -> FMA-bound, not LDG-bound.
// ============================================================
template<int CIN, int C>
__global__ __launch_bounds__(256) void msg_big(
    const float* __restrict__ x, const float* __restrict__ Wm,
    const float* __restrict__ bm, const float* __restrict__ att)
{
    constexpr int HC  = 1024;
    constexpr int H   = HC / C;
    constexpr int NPB = 8;
    constexpr int OPT = 4;

    __shared__ float x_s[NPB][CIN];
    __shared__ float att_s[HC];
    __shared__ float alpha_s[NPB * H];

    const int tid   = threadIdx.x;
    const int gbase = blockIdx.x * NPB;

    for (int i = tid; i < NPB * CIN; i += 256)
        x_s[i / CIN][i % CIN] = x[(size_t)gbase * CIN + i];
    for (int i = tid; i < HC; i += 256)
        att_s[i] = att[i];
    if (tid < NPB * H) alpha_s[tid] = 0.f;
    __syncthreads();

    float acc[NPB][OPT];
    #pragma unroll
    for (int n = 0; n < NPB; n++)
        #pragma unroll
        for (int j = 0; j < OPT; j++) acc[n][j] = 0.f;

    for (int k = 0; k < CIN; k++) {
        float w[OPT];
        #pragma unroll
        for (int j = 0; j < OPT; j++)
            w[j] = __ldg(&Wm[(size_t)k * HC + tid + j * 256]);
        #pragma unroll
        for (int n = 0; n < NPB; n++) {
            float xv = x_s[n][k];
            #pragma unroll
            for (int j = 0; j < OPT; j++)
                acc[n][j] = fmaf(xv, w[j], acc[n][j]);
        }
    }

    float bmv[OPT], attv[OPT];
    #pragma unroll
    for (int j = 0; j < OPT; j++) {
        bmv[j]  = __ldg(&bm[tid + j * 256]);
        attv[j] = att_s[tid + j * 256];
    }

    #pragma unroll
    for (int n = 0; n < NPB; n++) {
        #pragma unroll
        for (int j = 0; j < OPT; j++) {
            const int oo = tid + j * 256;
            float v = acc[n][j] + bmv[j];
            v = (v > 0.f) ? v : 0.01f * v;                 // leaky_relu(0.01)
            g_msg[(size_t)(gbase + n) * HC + oo] = v;
            // attention logit contribution; each warp's 32 outputs lie
            // entirely inside one head block (C is a multiple of 32)
            float contrib = v * attv[j];
            #pragma unroll
            for (int off = 16; off > 0; off >>= 1)
                contrib += __shfl_down_sync(0xffffffffu, contrib, off);
            if ((tid & 31) == 0)
                atomicAdd(&alpha_s[n * H + oo / C], contrib);
        }
    }
    __syncthreads();
    if (tid < NPB * H)
        g_alpha[(size_t)gbase * H + tid] = alpha_s[tid];
}

// ============================================================
// Phase A for layer 5: CIN=64, HC=32, H=1
// ============================================================
__global__ __launch_bounds__(256) void msg_small(
    const float* __restrict__ x, const float* __restrict__ Wm,
    const float* __restrict__ bm, const float* __restrict__ att)
{
    __shared__ float wm_s[64 * 32];
    const int tid = threadIdx.x;
    const int n   = tid >> 5;
    const int o   = tid & 31;
    const int g   = blockIdx.x * 8 + n;

    for (int i = tid; i < 64 * 32; i += 256) wm_s[i] = Wm[i];
    __syncthreads();

    const float* xr = x + (size_t)g * 64;
    float acc = 0.f;
    #pragma unroll
    for (int k = 0; k < 64; k++)
        acc = fmaf(__ldg(&xr[k]), wm_s[k * 32 + o], acc);
    acc += __ldg(&bm[o]);
    acc = (acc > 0.f) ? acc : 0.01f * acc;
    g_msg[(size_t)g * 32 + o] = acc;

    float c = acc * __ldg(&att[o]);
    #pragma unroll
    for (int off = 16; off > 0; off >>= 1)
        c += __shfl_down_sync(0xffffffffu, c, off);
    if (o == 0) g_alpha[g] = c;
}

// ============================================================
// Phase B: per-node 2-edge softmax aggregation + head mean +
// self loop (x @ Ws + bs) + optional ELU. One node per block.
// ============================================================
template<int CIN, int COUT, int H, bool DO_ELU>
__global__ __launch_bounds__(128) void agg(
    const float* __restrict__ x, const float* __restrict__ Ws,
    const float* __restrict__ bs, float* __restrict__ xout)
{
    constexpr int HC = H * COUT;
    const int g = blockIdx.x;
    const int n = g & (NCHAIN - 1);
    const bool hasL = (n > 0);
    const bool hasR = (n < NCHAIN - 1);

    __shared__ float x_s[CIN];
    __shared__ float wl[H];
    __shared__ float wr[H];

    const int tid = threadIdx.x;
    if (tid < CIN) x_s[tid] = x[(size_t)g * CIN + tid];
    if (tid < H) {
        float al = hasL ? g_alpha[(size_t)(g - 1) * H + tid] : -1e30f;
        float ar = hasR ? g_alpha[(size_t)(g + 1) * H + tid] : -1e30f;
        float m  = fmaxf(al, ar);
        float el = hasL ? expf(al - m) : 0.f;
        float er = hasR ? expf(ar - m) : 0.f;
        float inv = 1.f / (el + er + 1e-16f);
        wl[tid] = el * inv;
        wr[tid] = er * inv;
    }
    __syncthreads();

    const float* ml = g_msg + (size_t)(g - 1) * HC;
    const float* mr = g_msg + (size_t)(g + 1) * HC;

    for (int c = tid; c < COUT; c += 128) {
        float a = 0.f;
        #pragma unroll
        for (int h = 0; h < H; h++) {
            if (hasL) a = fmaf(wl[h], __ldg(&ml[h * COUT + c]), a);
            if (hasR) a = fmaf(wr[h], __ldg(&mr[h * COUT + c]), a);
        }
        a *= (1.f / H);                                    // head mean
        float s = 0.f;
        #pragma unroll 8
        for (int k = 0; k < CIN; k++)
            s = fmaf(x_s[k], __ldg(&Ws[k * COUT + c]), s);
        a += s + __ldg(&bs[c]);
        if (DO_ELU) a = (a > 0.f) ? a : expm1f(a);         // jax.nn.elu
        xout[(size_t)g * COUT + c] = a;
    }
}

// ============================================================
// Final: gather last node per graph (32 feats), write features
// and logits = out @ Wc + bc. Output layout: [logits(32), out(32x32)]
// ============================================================
__global__ __launch_bounds__(1024) void final_k(
    const float* __restrict__ x5, const float* __restrict__ Wc,
    const float* __restrict__ bc, float* __restrict__ out, int out_size)
{
    const int tid = threadIdx.x;         // 1024 threads = 32 graphs x 32 chan
    const int b = tid >> 5;
    const int c = tid & 31;
    float v = x5[((size_t)b * NCHAIN + (NCHAIN - 1)) * 32 + c];
    if (32 + tid < out_size) out[32 + tid] = v;
    float p = v * __ldg(&Wc[c]);
    #pragma unroll
    for (int off = 16; off > 0; off >>= 1)
        p += __shfl_down_sync(0xffffffffu, p, off);
    if (c == 0 && b < out_size) out[b] = p + __ldg(&bc[0]);
}

// ============================================================
// Launch
// ============================================================
extern "C" void kernel_launch(void* const* d_in, const int* in_sizes, int n_in,
                              void* d_out, int out_size)
{
    const float* nodes = (const float*)d_in[0];
    const float* Wm1 = (const float*)d_in[1];
    const float* bm1 = (const float*)d_in[2];
    const float* Ws1 = (const float*)d_in[3];
    const float* bs1 = (const float*)d_in[4];
    const float* att1 = (const float*)d_in[5];
    const float* Wm2 = (const float*)d_in[6];
    const float* bm2 = (const float*)d_in[7];
    const float* Ws2 = (const float*)d_in[8];
    const float* bs2 = (const float*)d_in[9];
    const float* att2 = (const float*)d_in[10];
    const float* Wm3 = (const float*)d_in[11];
    const float* bm3 = (const float*)d_in[12];
    const float* Ws3 = (const float*)d_in[13];
    const float* bs3 = (const float*)d_in[14];
    const float* att3 = (const float*)d_in[15];
    const float* Wm4 = (const float*)d_in[16];
    const float* bm4 = (const float*)d_in[17];
    const float* Ws4 = (const float*)d_in[18];
    const float* bs4 = (const float*)d_in[19];
    const float* att4 = (const float*)d_in[20];
    const float* Wm5 = (const float*)d_in[21];
    const float* bm5 = (const float*)d_in[22];
    const float* Ws5 = (const float*)d_in[23];
    const float* bs5 = (const float*)d_in[24];
    const float* att5 = (const float*)d_in[25];
    const float* Wc  = (const float*)d_in[26];
    const float* bc  = (const float*)d_in[27];

    float *bufA = nullptr, *bufB = nullptr;
    cudaGetSymbolAddress((void**)&bufA, g_bufA);
    cudaGetSymbolAddress((void**)&bufB, g_bufB);

    const int GB = NUMNODES / 8;   // msg kernel blocks

    // Layer 1: cin=1, cout=128, H=8
    msg_big<1, 128><<<GB, 256>>>(nodes, Wm1, bm1, att1);
    agg<1, 128, 8, true><<<NUMNODES, 128>>>(nodes, Ws1, bs1, bufA);

    // Layer 2: cin=128, cout=128, H=8
    msg_big<128, 128><<<GB, 256>>>(bufA, Wm2, bm2, att2);
    agg<128, 128, 8, true><<<NUMNODES, 128>>>(bufA, Ws2, bs2, bufB);

    // Layer 3: cin=128, cout=64, H=16
    msg_big<128, 64><<<GB, 256>>>(bufB, Wm3, bm3, att3);
    agg<128, 64, 16, true><<<NUMNODES, 128>>>(bufB, Ws3, bs3, bufA);

    // Layer 4: cin=64, cout=64, H=16
    msg_big<64, 64><<<GB, 256>>>(bufA, Wm4, bm4, att4);
    agg<64, 64, 16, true><<<NUMNODES, 128>>>(bufA, Ws4, bs4, bufB);

    // Layer 5: cin=64, cout=32, H=1 (no ELU)
    msg_small<<<GB, 256>>>(bufB, Wm5, bm5, att5);
    agg<64, 32, 1, false><<<NUMNODES, 128>>>(bufB, Ws5, bs5, bufA);

    // Readout
    final_k<<<1, 1024>>>(bufA, Wc, bc, (float*)d_out, out_size);
}

// round 2
// speedup vs baseline: 1.2818x; 1.2818x over previous
#include <cuda_runtime.h>
#include <cstddef>

#define NUMNODES 32768
#define NCHAIN   1024
#define YSTRIDE  1152   // 1024 msg cols + up to 128 self cols

// -------- global scratch (no allocations allowed) --------
__device__ float g_y[(size_t)NUMNODES * YSTRIDE];   // fused msg+self output, ~151 MB
__device__ float g_alpha[(size_t)NUMNODES * 16];    // attention logits per (node, head)
__device__ float g_bufA[(size_t)NUMNODES * 128];    // activation double buffer
__device__ float g_bufB[(size_t)NUMNODES * 128];

// -------- packed f32x2 helpers (sm_100+) --------
__device__ __forceinline__ unsigned long long pack2(float lo, float hi) {
    unsigned long long r;
    asm("mov.b64 %0, {%1, %2};" : "=l"(r) : "f"(lo), "f"(hi));
    return r;
}
__device__ __forceinline__ void unpack2(unsigned long long v, float& lo, float& hi) {
    asm("mov.b64 {%0, %1}, %2;" : "=f"(lo), "=f"(hi) : "l"(v));
}
__device__ __forceinline__ unsigned long long fma2(unsigned long long a,
                                                   unsigned long long b,
                                                   unsigned long long c) {
    unsigned long long d;
    asm("fma.rn.f32x2 %0, %1, %2, %3;" : "=l"(d) : "l"(a), "l"(b), "l"(c));
    return d;
}

// ============================================================
// Fused GEMM (layers 1-4):
//   y[:, 0:1024]          = leaky_relu(x @ Wm + bm)   (msg, H*C = 1024)
//   y[:, 1024:1024+COUT]  = x @ Ws + bs               (self)
//   g_alpha[g,h]          = <msg[g,h,:], att[h,:]>
// Tile: 128 nodes x 128 cols per 256-thread block; per-thread
// 8x8 register tile held as 8x4 packed f32x2 accumulators.
// ============================================================
template<int CIN, int COUT, int C>
__global__ __launch_bounds__(256, 2) void gemm_msg(
    const float* __restrict__ x,  const float* __restrict__ Wm,
    const float* __restrict__ bm, const float* __restrict__ Ws,
    const float* __restrict__ bs, const float* __restrict__ att,
    float* __restrict__ y)
{
    constexpr int H  = 1024 / C;
    constexpr int KT = (CIN < 16) ? CIN : 16;
    constexpr int MT = 128;
    constexpr int NT = 128;

    __shared__ unsigned long long x_s[MT * KT];   // x duplicated {v,v}
    __shared__ float              w_s[KT * NT];

    const int tid = threadIdx.x;
    const int tn  = tid & 15;
    const int tm  = tid >> 4;
    const int mBase = blockIdx.x * MT;
    const int nBase = blockIdx.y * NT;
    const bool isMsg = (nBase < 1024);

    // acc init with bias (identical per node row)
    unsigned long long acc[8][4];
    #pragma unroll
    for (int j = 0; j < 4; j++) {
        const int n0 = nBase + tn * 8 + 2 * j;
        float b0, b1;
        if (n0 < 1024)            b0 = __ldg(&bm[n0]);
        else if (n0 < 1024 + COUT) b0 = __ldg(&bs[n0 - 1024]);
        else                      b0 = 0.f;
        const int n1 = n0 + 1;
        if (n1 < 1024)            b1 = __ldg(&bm[n1]);
        else if (n1 < 1024 + COUT) b1 = __ldg(&bs[n1 - 1024]);
        else                      b1 = 0.f;
        const unsigned long long bb = pack2(b0, b1);
        #pragma unroll
        for (int i = 0; i < 8; i++) acc[i][j] = bb;
    }

    for (int kt = 0; kt < CIN; kt += KT) {
        __syncthreads();
        // load x tile (MT x KT), duplicated into f32x2
        constexpr int XIT = (MT * KT + 255) / 256;
        #pragma unroll
        for (int i = 0; i < XIT; i++) {
            const int idx = tid + i * 256;
            if ((MT * KT % 256 == 0) || idx < MT * KT) {
                const int mm = idx / KT, kk = idx % KT;
                const float v = x[(size_t)(mBase + mm) * CIN + kt + kk];
                x_s[mm * KT + kk] = pack2(v, v);
            }
        }
        // load w tile (KT x NT) — gather from Wm | Ws | zero-pad
        constexpr int WIT = (KT * NT + 255) / 256;
        #pragma unroll
        for (int i = 0; i < WIT; i++) {
            const int idx = tid + i * 256;
            if ((KT * NT % 256 == 0) || idx < KT * NT) {
                const int kk = idx / NT, nn = idx % NT;
                const int n = nBase + nn, k = kt + kk;
                float wv;
                if (n < 1024)             wv = Wm[(size_t)k * 1024 + n];
                else if (n < 1024 + COUT) wv = Ws[(size_t)k * COUT + (n - 1024)];
                else                      wv = 0.f;
                w_s[kk * NT + nn] = wv;
            }
        }
        __syncthreads();

        #pragma unroll
        for (int k = 0; k < KT; k++) {
            unsigned long long ww[4];
            const unsigned long long* w2 =
                reinterpret_cast<const unsigned long long*>(w_s + k * NT);
            #pragma unroll
            for (int j = 0; j < 4; j++) ww[j] = w2[tn * 4 + j];
            #pragma unroll
            for (int i = 0; i < 8; i++) {
                const unsigned long long xx = x_s[(tm * 8 + i) * KT + k];
                #pragma unroll
                for (int j = 0; j < 4; j++)
                    acc[i][j] = fma2(xx, ww[j], acc[i][j]);
            }
        }
    }

    // epilogue: leaky_relu on msg, alpha reduction, stores
    #pragma unroll
    for (int i = 0; i < 8; i++) {
        const int m = mBase + tm * 8 + i;
        float v[8];
        #pragma unroll
        for (int j = 0; j < 4; j++) unpack2(acc[i][j], v[2 * j], v[2 * j + 1]);

        float ap = 0.f;
        if (isMsg) {
            #pragma unroll
            for (int e = 0; e < 8; e++) {
                const int n = nBase + tn * 8 + e;
                float vv = v[e];
                vv = (vv > 0.f) ? vv : 0.01f * vv;
                v[e] = vv;
                ap = fmaf(vv, __ldg(&att[n]), ap);
            }
        }
        float4* dst = reinterpret_cast<float4*>(y + (size_t)m * YSTRIDE + nBase + tn * 8);
        dst[0] = make_float4(v[0], v[1], v[2], v[3]);
        dst[1] = make_float4(v[4], v[5], v[6], v[7]);

        if (isMsg) {
            ap += __shfl_xor_sync(0xffffffffu, ap, 1);
            ap += __shfl_xor_sync(0xffffffffu, ap, 2);
            ap += __shfl_xor_sync(0xffffffffu, ap, 4);
            if (C == 128) ap += __shfl_xor_sync(0xffffffffu, ap, 8);
            constexpr int LPH = C / 8;       // lanes per head: 16 (C=128) or 8 (C=64)
            if ((tn & (LPH - 1)) == 0) {
                const int h = (nBase + tn * 8) / C;
                g_alpha[(size_t)m * H + h] = ap;
            }
        }
    }
}

// ============================================================
// Layer 5 fused msg+self: CIN=64, msg C=32 (H=1), self 32.
// y row stride 64: [msg(32) | self(32)]
// ============================================================
__global__ __launch_bounds__(256) void msg5(
    const float* __restrict__ x,  const float* __restrict__ Wm,
    const float* __restrict__ bm, const float* __restrict__ Ws,
    const float* __restrict__ bs, const float* __restrict__ att,
    float* __restrict__ y)
{
    __shared__ float wm_s[64 * 32];
    __shared__ float ws_s[64 * 32];
    __shared__ float x_s[8 * 64];

    const int tid = threadIdx.x;
    const int n = tid >> 5, o = tid & 31;
    const int gBase = blockIdx.x * 8;

    for (int i = tid; i < 64 * 32; i += 256) { wm_s[i] = Wm[i]; ws_s[i] = Ws[i]; }
    for (int i = tid; i < 8 * 64; i += 256)  x_s[i] = x[(size_t)gBase * 64 + i];
    __syncthreads();

    float am = __ldg(&bm[o]);
    float as = __ldg(&bs[o]);
    #pragma unroll
    for (int k = 0; k < 64; k++) {
        const float xv = x_s[n * 64 + k];
        am = fmaf(xv, wm_s[k * 32 + o], am);
        as = fmaf(xv, ws_s[k * 32 + o], as);
    }
    am = (am > 0.f) ? am : 0.01f * am;
    const int g = gBase + n;
    y[(size_t)g * 64 + o]      = am;
    y[(size_t)g * 64 + 32 + o] = as;

    float a = am * __ldg(&att[o]);
    #pragma unroll
    for (int off = 16; off > 0; off >>= 1)
        a += __shfl_xor_sync(0xffffffffu, a, off);
    if (o == 0) g_alpha[g] = a;
}

// ============================================================
// Aggregation stencil: 2-edge segment softmax + head mean +
// self + optional ELU. Pure memory-bound.
// ============================================================
template<int C, int H, int STRIDE, bool ELU>
__global__ __launch_bounds__(256) void agg2(
    const float* __restrict__ y, float* __restrict__ xout)
{
    constexpr int COUT = C;
    constexpr int TPN  = COUT / 4;       // threads per node (float4)
    constexpr int NPB  = 256 / TPN;      // nodes per block
    constexpr int SELF = H * C;          // self offset within y row

    __shared__ float wl_s[NPB * H];
    __shared__ float wr_s[NPB * H];

    const int tid = threadIdx.x;
    const int gBase = blockIdx.x * NPB;

    if (tid < NPB * H) {
        const int node = tid / H, h = tid % H;
        const int g = gBase + node;
        const int nch = g & (NCHAIN - 1);
        float el, er;
        if (nch == 0)                { el = 0.f; er = 1.f; }
        else if (nch == NCHAIN - 1)  { el = 1.f; er = 0.f; }
        else {
            const float al = g_alpha[(size_t)(g - 1) * H + h];
            const float ar = g_alpha[(size_t)(g + 1) * H + h];
            const float mx = fmaxf(al, ar);
            el = expf(al - mx);
            er = expf(ar - mx);
        }
        const float inv = (1.f / ((el + er) + 1e-16f)) * (1.f / H);
        wl_s[tid] = el * inv;
        wr_s[tid] = er * inv;
    }
    __syncthreads();

    const int lane = tid % TPN, node = tid / TPN;
    const int g = gBase + node;
    const int nch = g & (NCHAIN - 1);
    const float* rowL = y + (size_t)((nch > 0)          ? g - 1 : g) * STRIDE;
    const float* rowR = y + (size_t)((nch < NCHAIN - 1) ? g + 1 : g) * STRIDE;
    const int c4 = lane * 4;

    float4 acc = make_float4(0.f, 0.f, 0.f, 0.f);
    #pragma unroll
    for (int h = 0; h < H; h++) {
        const float wl = wl_s[node * H + h];
        const float wr = wr_s[node * H + h];
        const float4 mL = *reinterpret_cast<const float4*>(rowL + h * C + c4);
        const float4 mR = *reinterpret_cast<const float4*>(rowR + h * C + c4);
        acc.x = fmaf(wl, mL.x, fmaf(wr, mR.x, acc.x));
        acc.y = fmaf(wl, mL.y, fmaf(wr, mR.y, acc.y));
        acc.z = fmaf(wl, mL.z, fmaf(wr, mR.z, acc.z));
        acc.w = fmaf(wl, mL.w, fmaf(wr, mR.w, acc.w));
    }
    const float4 sv = *reinterpret_cast<const float4*>(y + (size_t)g * STRIDE + SELF + c4);
    acc.x += sv.x; acc.y += sv.y; acc.z += sv.z; acc.w += sv.w;
    if (ELU) {
        acc.x = (acc.x > 0.f) ? acc.x : expm1f(acc.x);
        acc.y = (acc.y > 0.f) ? acc.y : expm1f(acc.y);
        acc.z = (acc.z > 0.f) ? acc.z : expm1f(acc.z);
        acc.w = (acc.w > 0.f) ? acc.w : expm1f(acc.w);
    }
    *reinterpret_cast<float4*>(xout + (size_t)g * COUT + c4) = acc;
}

// ============================================================
// Final readout: last node per graph -> features + logits.
// Output layout: [logits(32), out(32x32)]
// ============================================================
__global__ __launch_bounds__(1024) void final_k(
    const float* __restrict__ x5, const float* __restrict__ Wc,
    const float* __restrict__ bc, float* __restrict__ out, int out_size)
{
    const int tid = threadIdx.x;
    const int b = tid >> 5;
    const int c = tid & 31;
    const float v = x5[((size_t)b * NCHAIN + (NCHAIN - 1)) * 32 + c];
    if (32 + tid < out_size) out[32 + tid] = v;
    float p = v * __ldg(&Wc[c]);
    #pragma unroll
    for (int off = 16; off > 0; off >>= 1)
        p += __shfl_down_sync(0xffffffffu, p, off);
    if (c == 0 && b < out_size) out[b] = p + __ldg(&bc[0]);
}

// ============================================================
// Launch
// ============================================================
extern "C" void kernel_launch(void* const* d_in, const int* in_sizes, int n_in,
                              void* d_out, int out_size)
{
    const float* nodes = (const float*)d_in[0];
    const float* Wm1 = (const float*)d_in[1];
    const float* bm1 = (const float*)d_in[2];
    const float* Ws1 = (const float*)d_in[3];
    const float* bs1 = (const float*)d_in[4];
    const float* att1 = (const float*)d_in[5];
    const float* Wm2 = (const float*)d_in[6];
    const float* bm2 = (const float*)d_in[7];
    const float* Ws2 = (const float*)d_in[8];
    const float* bs2 = (const float*)d_in[9];
    const float* att2 = (const float*)d_in[10];
    const float* Wm3 = (const float*)d_in[11];
    const float* bm3 = (const float*)d_in[12];
    const float* Ws3 = (const float*)d_in[13];
    const float* bs3 = (const float*)d_in[14];
    const float* att3 = (const float*)d_in[15];
    const float* Wm4 = (const float*)d_in[16];
    const float* bm4 = (const float*)d_in[17];
    const float* Ws4 = (const float*)d_in[18];
    const float* bs4 = (const float*)d_in[19];
    const float* att4 = (const float*)d_in[20];
    const float* Wm5 = (const float*)d_in[21];
    const float* bm5 = (const float*)d_in[22];
    const float* Ws5 = (const float*)d_in[23];
    const float* bs5 = (const float*)d_in[24];
    const float* att5 = (const float*)d_in[25];
    const float* Wc  = (const float*)d_in[26];
    const float* bc  = (const float*)d_in[27];

    float *yb = nullptr, *bufA = nullptr, *bufB = nullptr;
    cudaGetSymbolAddress((void**)&yb,   g_y);
    cudaGetSymbolAddress((void**)&bufA, g_bufA);
    cudaGetSymbolAddress((void**)&bufB, g_bufB);

    const dim3 GG(NUMNODES / 128, 9);

    // Layer 1: cin=1, cout=128, H=8, C=128
    gemm_msg<1, 128, 128><<<GG, 256>>>(nodes, Wm1, bm1, Ws1, bs1, att1, yb);
    agg2<128, 8, YSTRIDE, true><<<NUMNODES / 8, 256>>>(yb, bufA);

    // Layer 2: cin=128, cout=128, H=8, C=128
    gemm_msg<128, 128, 128><<<GG, 256>>>(bufA, Wm2, bm2, Ws2, bs2, att2, yb);
    agg2<128, 8, YSTRIDE, true><<<NUMNODES / 8, 256>>>(yb, bufB);

    // Layer 3: cin=128, cout=64, H=16, C=64
    gemm_msg<128, 64, 64><<<GG, 256>>>(bufB, Wm3, bm3, Ws3, bs3, att3, yb);
    agg2<64, 16, YSTRIDE, true><<<NUMNODES / 16, 256>>>(yb, bufA);

    // Layer 4: cin=64, cout=64, H=16, C=64
    gemm_msg<64, 64, 64><<<GG, 256>>>(bufA, Wm4, bm4, Ws4, bs4, att4, yb);
    agg2<64, 16, YSTRIDE, true><<<NUMNODES / 16, 256>>>(yb, bufB);

    // Layer 5: cin=64, cout=32, H=1, C=32 (no ELU)
    msg5<<<NUMNODES / 8, 256>>>(bufB, Wm5, bm5, Ws5, bs5, att5, yb);
    agg2<32, 1, 64, false><<<NUMNODES / 32, 256>>>(yb, bufA);

    // Readout
    final_k<<<1, 1024>>>(bufA, Wc, bc, (float*)d_out, out_size);
}

// round 4
// speedup vs baseline: 2.6744x; 2.0865x over previous
#include <cuda_runtime.h>
#include <cuda_bf16.h>
#include <cstdint>
#include <cstddef>

#define NUMNODES 32768
#define NCHAIN   1024
#define YSTRIDE  1152

// -------- global scratch (no allocations allowed) --------
__device__ float g_y[(size_t)NUMNODES * YSTRIDE];      // fused msg+self output
__device__ float g_alpha[(size_t)NUMNODES * 16];       // attention logits
__device__ float g_bufA[(size_t)NUMNODES * 128];
__device__ float g_bufB[(size_t)NUMNODES * 128];
__device__ __nv_bfloat16 g_xh[(size_t)NUMNODES * 128]; // split activations
__device__ __nv_bfloat16 g_xl[(size_t)NUMNODES * 128];
#define WSLOT (1152 * 128)
__device__ __nv_bfloat16 g_wh[3 * WSLOT];              // split transposed weights [n][k]
__device__ __nv_bfloat16 g_wl[3 * WSLOT];
__device__ float g_bias[3 * 1152];

// ================= PTX helpers (baseline ISA only) =================
__device__ __forceinline__ uint32_t smem_u32(const void* p) {
    uint32_t a;
    asm("{ .reg .u64 t; cvta.to.shared.u64 t, %1; cvt.u32.u64 %0, t; }" : "=r"(a) : "l"(p));
    return a;
}
__device__ __forceinline__ void ldm_x4(uint32_t* r, uint32_t addr) {
    asm volatile("ldmatrix.sync.aligned.m8n8.x4.shared.b16 {%0,%1,%2,%3}, [%4];"
        : "=r"(r[0]), "=r"(r[1]), "=r"(r[2]), "=r"(r[3]) : "r"(addr));
}
__device__ __forceinline__ void ldm_x2(uint32_t* r, uint32_t addr) {
    asm volatile("ldmatrix.sync.aligned.m8n8.x2.shared.b16 {%0,%1}, [%2];"
        : "=r"(r[0]), "=r"(r[1]) : "r"(addr));
}
__device__ __forceinline__ void mma_bf16(float* d, const uint32_t* a, const uint32_t* b) {
    asm volatile(
        "mma.sync.aligned.m16n8k16.row.col.f32.bf16.bf16.f32 "
        "{%0,%1,%2,%3}, {%4,%5,%6,%7}, {%8,%9}, {%0,%1,%2,%3};"
        : "+f"(d[0]), "+f"(d[1]), "+f"(d[2]), "+f"(d[3])
        : "r"(a[0]), "r"(a[1]), "r"(a[2]), "r"(a[3]), "r"(b[0]), "r"(b[1]));
}

// ================= weight split + gather to [n][k] =================
template<int K, int COUT>
__global__ __launch_bounds__(256) void convert_w(
    const float* __restrict__ Wm, const float* __restrict__ bm,
    const float* __restrict__ Ws, const float* __restrict__ bs,
    __nv_bfloat16* __restrict__ wh, __nv_bfloat16* __restrict__ wl,
    float* __restrict__ bias)
{
    const int idx = blockIdx.x * 256 + threadIdx.x;
    if (idx >= 1152 * K) return;
    const int n = idx / K, k = idx % K;
    float v;
    if (n < 1024)             v = Wm[(size_t)k * 1024 + n];
    else if (n < 1024 + COUT) v = Ws[(size_t)k * COUT + (n - 1024)];
    else                      v = 0.f;
    const __nv_bfloat16 h = __float2bfloat16(v);
    wh[idx] = h;
    wl[idx] = __float2bfloat16(v - __bfloat162float(h));
    if (k == 0)
        bias[n] = (n < 1024) ? bm[n] : ((n < 1024 + COUT) ? bs[n - 1024] : 0.f);
}

// ================= mma.sync fused GEMM (layers 2-4) =================
// y_tile[128m x 128n] = split-bf16( x[128 x K] @ w^T[K x 128] ) + bias
// msg cols get leaky_relu + attention-logit reduction.
template<int K, int C>
__global__ __launch_bounds__(256) void gemm_mma(
    const __nv_bfloat16* __restrict__ xh, const __nv_bfloat16* __restrict__ xl,
    const __nv_bfloat16* __restrict__ wh, const __nv_bfloat16* __restrict__ wl,
    const float* __restrict__ bias, const float* __restrict__ att,
    float* __restrict__ y)
{
    constexpr int SROW = K + 8;          // bf16 elements per smem row (stride)
    constexpr int MATB = 128 * SROW;     // bf16 per matrix
    extern __shared__ __align__(16) char smem[];
    __nv_bfloat16* sAh = reinterpret_cast<__nv_bfloat16*>(smem);
    __nv_bfloat16* sAl = sAh + MATB;
    __nv_bfloat16* sBh = sAl + MATB;
    __nv_bfloat16* sBl = sBh + MATB;
    float* alpha_s = reinterpret_cast<float*>(sBl + MATB);   // [2][128]

    const int tid  = threadIdx.x;
    const int lane = tid & 31;
    const int wid  = tid >> 5;
    const int warpM = wid >> 1;          // 0..3
    const int warpN = wid & 1;           // 0..1
    const int g = lane >> 2, t = lane & 3;

    const int mBase = blockIdx.x * 128;
    const int nBase = blockIdx.y * 128;
    const bool isMsg = (nBase < 1024);

    // ---- cooperative loads: 4 matrices, vectorized 16B ----
    {
        constexpr int VPR = K / 8;                // uint4 per row
        constexpr int TOT = 128 * VPR;
        const uint4* gAh = reinterpret_cast<const uint4*>(xh + (size_t)mBase * K);
        const uint4* gAl = reinterpret_cast<const uint4*>(xl + (size_t)mBase * K);
        const uint4* gBh = reinterpret_cast<const uint4*>(wh + (size_t)nBase * K);
        const uint4* gBl = reinterpret_cast<const uint4*>(wl + (size_t)nBase * K);
        #pragma unroll
        for (int i = 0; i < TOT / 256; i++) {
            const int idx = tid + i * 256;
            const int row = idx / VPR, kv = idx % VPR;
            const int so = (row * SROW) / 8 + kv;
            reinterpret_cast<uint4*>(sAh)[so] = gAh[idx];
            reinterpret_cast<uint4*>(sAl)[so] = gAl[idx];
            reinterpret_cast<uint4*>(sBh)[so] = gBh[idx];
            reinterpret_cast<uint4*>(sBl)[so] = gBl[idx];
        }
    }
    __syncthreads();

    // ---- main MMA loop ----
    float acc[2][8][4];
    #pragma unroll
    for (int mi = 0; mi < 2; mi++)
        #pragma unroll
        for (int ni = 0; ni < 8; ni++)
            #pragma unroll
            for (int e = 0; e < 4; e++) acc[mi][ni][e] = 0.f;

    const uint32_t uAh = smem_u32(sAh), uAl = smem_u32(sAl);
    const uint32_t uBh = smem_u32(sBh), uBl = smem_u32(sBl);
    // per-lane ldmatrix row/col offsets (bytes)
    const uint32_t aOfs = ((warpM * 32 + (lane & 15)) * SROW + ((lane >> 4) << 3)) * 2;
    const uint32_t bOfs = ((warpN * 64 + (lane & 7)) * SROW + (((lane >> 3) & 1) << 3)) * 2;

    #pragma unroll
    for (int kc = 0; kc < K / 16; kc++) {
        const uint32_t kByte = kc * 32;   // 16 bf16
        uint32_t ah[2][4], al[2][4];
        #pragma unroll
        for (int mi = 0; mi < 2; mi++) {
            const uint32_t ro = aOfs + mi * (16 * SROW * 2) + kByte;
            ldm_x4(ah[mi], uAh + ro);
            ldm_x4(al[mi], uAl + ro);
        }
        #pragma unroll
        for (int ni = 0; ni < 8; ni++) {
            const uint32_t ro = bOfs + ni * (8 * SROW * 2) + kByte;
            uint32_t bh[2], bl[2];
            ldm_x2(bh, uBh + ro);
            ldm_x2(bl, uBl + ro);
            #pragma unroll
            for (int mi = 0; mi < 2; mi++) {
                mma_bf16(acc[mi][ni], ah[mi], bh);
                mma_bf16(acc[mi][ni], ah[mi], bl);
                mma_bf16(acc[mi][ni], al[mi], bh);
            }
        }
    }

    // ---- epilogue: bias, leaky, alpha, stores ----
    float alphaLoc[2][2] = {{0.f, 0.f}, {0.f, 0.f}};   // [mi][row-half]

    #pragma unroll
    for (int ni = 0; ni < 8; ni++) {
        const int n0 = nBase + warpN * 64 + ni * 8 + 2 * t;
        const float2 bb = *reinterpret_cast<const float2*>(&bias[n0]);
        float2 aa = make_float2(0.f, 0.f);
        if (isMsg) aa = *reinterpret_cast<const float2*>(&att[n0]);
        #pragma unroll
        for (int mi = 0; mi < 2; mi++) {
            float v0 = acc[mi][ni][0] + bb.x;
            float v1 = acc[mi][ni][1] + bb.y;
            float v2 = acc[mi][ni][2] + bb.x;
            float v3 = acc[mi][ni][3] + bb.y;
            if (isMsg) {
                v0 = (v0 > 0.f) ? v0 : 0.01f * v0;
                v1 = (v1 > 0.f) ? v1 : 0.01f * v1;
                v2 = (v2 > 0.f) ? v2 : 0.01f * v2;
                v3 = (v3 > 0.f) ? v3 : 0.01f * v3;
                alphaLoc[mi][0] = fmaf(v0, aa.x, fmaf(v1, aa.y, alphaLoc[mi][0]));
                alphaLoc[mi][1] = fmaf(v2, aa.x, fmaf(v3, aa.y, alphaLoc[mi][1]));
            }
            const int row0 = mBase + warpM * 32 + mi * 16 + g;
            *reinterpret_cast<float2*>(y + (size_t)row0 * YSTRIDE + n0) = make_float2(v0, v1);
            *reinterpret_cast<float2*>(y + (size_t)(row0 + 8) * YSTRIDE + n0) = make_float2(v2, v3);
        }
    }

    if (isMsg) {
        // reduce alpha over quad (t lanes)
        #pragma unroll
        for (int mi = 0; mi < 2; mi++)
            #pragma unroll
            for (int rh = 0; rh < 2; rh++) {
                float s = alphaLoc[mi][rh];
                s += __shfl_xor_sync(0xffffffffu, s, 1);
                s += __shfl_xor_sync(0xffffffffu, s, 2);
                alphaLoc[mi][rh] = s;
            }
        if (C == 64) {
            // one head per warp's 64-col span
            const int h = blockIdx.y * 2 + warpN;
            if (t == 0) {
                #pragma unroll
                for (int mi = 0; mi < 2; mi++) {
                    const int row0 = mBase + warpM * 32 + mi * 16 + g;
                    g_alpha[(size_t)row0 * 16 + h]       = alphaLoc[mi][0];
                    g_alpha[(size_t)(row0 + 8) * 16 + h] = alphaLoc[mi][1];
                }
            }
        } else {
            // C==128: head spans both N-warps -> combine via smem
            if (t == 0) {
                #pragma unroll
                for (int mi = 0; mi < 2; mi++) {
                    const int lr = warpM * 32 + mi * 16 + g;
                    alpha_s[warpN * 128 + lr]     = alphaLoc[mi][0];
                    alpha_s[warpN * 128 + lr + 8] = alphaLoc[mi][1];
                }
            }
            __syncthreads();
            if (tid < 128)
                g_alpha[(size_t)(mBase + tid) * 8 + blockIdx.y] =
                    alpha_s[tid] + alpha_s[128 + tid];
        }
    }
}

// ================= layer-1 SIMT GEMM (K=1 outer product) =================
__global__ __launch_bounds__(256, 2) void gemm_l1(
    const float* __restrict__ x,  const float* __restrict__ Wm,
    const float* __restrict__ bm, const float* __restrict__ Ws,
    const float* __restrict__ bs, const float* __restrict__ att,
    float* __restrict__ y)
{
    __shared__ float w_s[128], b_s[128], a_s[128];
    const int tid = threadIdx.x;
    const int mBase = blockIdx.x * 128;
    const int nBase = blockIdx.y * 128;
    const bool isMsg = (nBase < 1024);

    if (tid < 128) {
        const int n = nBase + tid;
        if (n < 1024)      { w_s[tid] = Wm[n]; b_s[tid] = bm[n]; a_s[tid] = att[n]; }
        else if (n < 1152) { w_s[tid] = Ws[n - 1024]; b_s[tid] = bs[n - 1024]; a_s[tid] = 0.f; }
    }
    __syncthreads();

    const int r  = tid >> 1;
    const int half = (tid & 1) * 64;
    const int m = mBase + r;
    const float xv = x[m];
    float* yrow = y + (size_t)m * YSTRIDE + nBase + half;
    float alpha = 0.f;
    #pragma unroll
    for (int j = 0; j < 64; j += 4) {
        float vv[4];
        #pragma unroll
        for (int e = 0; e < 4; e++) {
            float tt = fmaf(xv, w_s[half + j + e], b_s[half + j + e]);
            if (isMsg) { tt = (tt > 0.f) ? tt : 0.01f * tt; alpha = fmaf(tt, a_s[half + j + e], alpha); }
            vv[e] = tt;
        }
        *reinterpret_cast<float4*>(yrow + j) = make_float4(vv[0], vv[1], vv[2], vv[3]);
    }
    if (isMsg) {
        alpha += __shfl_xor_sync(0xffffffffu, alpha, 1);
        if ((tid & 1) == 0) g_alpha[(size_t)m * 8 + blockIdx.y] = alpha;
    }
}

// ================= layer 5 msg+self =================
__global__ __launch_bounds__(256) void msg5(
    const float* __restrict__ x,  const float* __restrict__ Wm,
    const float* __restrict__ bm, const float* __restrict__ Ws,
    const float* __restrict__ bs, const float* __restrict__ att,
    float* __restrict__ y)
{
    __shared__ float wm_s[64 * 32];
    __shared__ float ws_s[64 * 32];
    __shared__ float x_s[8 * 64];

    const int tid = threadIdx.x;
    const int n = tid >> 5, o = tid & 31;
    const int gBase = blockIdx.x * 8;

    for (int i = tid; i < 64 * 32; i += 256) { wm_s[i] = Wm[i]; ws_s[i] = Ws[i]; }
    for (int i = tid; i < 8 * 64; i += 256)  x_s[i] = x[(size_t)gBase * 64 + i];
    __syncthreads();

    float am = __ldg(&bm[o]);
    float as = __ldg(&bs[o]);
    #pragma unroll
    for (int k = 0; k < 64; k++) {
        const float xv = x_s[n * 64 + k];
        am = fmaf(xv, wm_s[k * 32 + o], am);
        as = fmaf(xv, ws_s[k * 32 + o], as);
    }
    am = (am > 0.f) ? am : 0.01f * am;
    const int gg = gBase + n;
    y[(size_t)gg * 64 + o]      = am;
    y[(size_t)gg * 64 + 32 + o] = as;

    float a = am * __ldg(&att[o]);
    #pragma unroll
    for (int off = 16; off > 0; off >>= 1)
        a += __shfl_xor_sync(0xffffffffu, a, off);
    if (o == 0) g_alpha[gg] = a;
}

// ================= aggregation stencil =================
template<int C, int H, int STRIDE, bool ELU, bool SPLIT>
__global__ __launch_bounds__(256) void agg2(
    const float* __restrict__ y, float* __restrict__ xout,
    __nv_bfloat16* __restrict__ xh, __nv_bfloat16* __restrict__ xl)
{
    constexpr int COUT = C;
    constexpr int TPN  = COUT / 4;
    constexpr int NPB  = 256 / TPN;
    constexpr int SELF = H * C;

    __shared__ float wl_s[NPB * H];
    __shared__ float wr_s[NPB * H];

    const int tid = threadIdx.x;
    const int gBase = blockIdx.x * NPB;

    if (tid < NPB * H) {
        const int node = tid / H, h = tid % H;
        const int g = gBase + node;
        const int nch = g & (NCHAIN - 1);
        float el, er;
        if (nch == 0)               { el = 0.f; er = 1.f; }
        else if (nch == NCHAIN - 1) { el = 1.f; er = 0.f; }
        else {
            const float al = g_alpha[(size_t)(g - 1) * H + h];
            const float ar = g_alpha[(size_t)(g + 1) * H + h];
            const float mx = fmaxf(al, ar);
            el = expf(al - mx);
            er = expf(ar - mx);
        }
        const float inv = (1.f / ((el + er) + 1e-16f)) * (1.f / H);
        wl_s[tid] = el * inv;
        wr_s[tid] = er * inv;
    }
    __syncthreads();

    const int lane = tid % TPN, node = tid / TPN;
    const int g = gBase + node;
    const int nch = g & (NCHAIN - 1);
    const float* rowL = y + (size_t)((nch > 0)          ? g - 1 : g) * STRIDE;
    const float* rowR = y + (size_t)((nch < NCHAIN - 1) ? g + 1 : g) * STRIDE;
    const int c4 = lane * 4;

    float4 acc = make_float4(0.f, 0.f, 0.f, 0.f);
    #pragma unroll
    for (int h = 0; h < H; h++) {
        const float wl = wl_s[node * H + h];
        const float wr = wr_s[node * H + h];
        const float4 mL = *reinterpret_cast<const float4*>(rowL + h * C + c4);
        const float4 mR = *reinterpret_cast<const float4*>(rowR + h * C + c4);
        acc.x = fmaf(wl, mL.x, fmaf(wr, mR.x, acc.x));
        acc.y = fmaf(wl, mL.y, fmaf(wr, mR.y, acc.y));
        acc.z = fmaf(wl, mL.z, fmaf(wr, mR.z, acc.z));
        acc.w = fmaf(wl, mL.w, fmaf(wr, mR.w, acc.w));
    }
    const float4 sv = *reinterpret_cast<const float4*>(y + (size_t)g * STRIDE + SELF + c4);
    acc.x += sv.x; acc.y += sv.y; acc.z += sv.z; acc.w += sv.w;
    if (ELU) {
        acc.x = (acc.x > 0.f) ? acc.x : expm1f(acc.x);
        acc.y = (acc.y > 0.f) ? acc.y : expm1f(acc.y);
        acc.z = (acc.z > 0.f) ? acc.z : expm1f(acc.z);
        acc.w = (acc.w > 0.f) ? acc.w : expm1f(acc.w);
    }
    *reinterpret_cast<float4*>(xout + (size_t)g * COUT + c4) = acc;

    if (SPLIT) {
        const float vv[4] = {acc.x, acc.y, acc.z, acc.w};
        __nv_bfloat16 hv[4], lv[4];
        #pragma unroll
        for (int e = 0; e < 4; e++) {
            hv[e] = __float2bfloat16(vv[e]);
            lv[e] = __float2bfloat16(vv[e] - __bfloat162float(hv[e]));
        }
        *reinterpret_cast<uint2*>(xh + (size_t)g * COUT + c4) = *reinterpret_cast<uint2*>(hv);
        *reinterpret_cast<uint2*>(xl + (size_t)g * COUT + c4) = *reinterpret_cast<uint2*>(lv);
    }
}

// ================= readout =================
__global__ __launch_bounds__(1024) void final_k(
    const float* __restrict__ x5, const float* __restrict__ Wc,
    const float* __restrict__ bc, float* __restrict__ out, int out_size)
{
    const int tid = threadIdx.x;
    const int b = tid >> 5;
    const int c = tid & 31;
    const float v = x5[((size_t)b * NCHAIN + (NCHAIN - 1)) * 32 + c];
    if (32 + tid < out_size) out[32 + tid] = v;
    float p = v * __ldg(&Wc[c]);
    #pragma unroll
    for (int off = 16; off > 0; off >>= 1)
        p += __shfl_down_sync(0xffffffffu, p, off);
    if (c == 0 && b < out_size) out[b] = p + __ldg(&bc[0]);
}

// ================= launch =================
extern "C" void kernel_launch(void* const* d_in, const int* in_sizes, int n_in,
                              void* d_out, int out_size)
{
    const float* nodes = (const float*)d_in[0];
    const float* Wm1 = (const float*)d_in[1];  const float* bm1 = (const float*)d_in[2];
    const float* Ws1 = (const float*)d_in[3];  const float* bs1 = (const float*)d_in[4];
    const float* att1 = (const float*)d_in[5];
    const float* Wm2 = (const float*)d_in[6];  const float* bm2 = (const float*)d_in[7];
    const float* Ws2 = (const float*)d_in[8];  const float* bs2 = (const float*)d_in[9];
    const float* att2 = (const float*)d_in[10];
    const float* Wm3 = (const float*)d_in[11]; const float* bm3 = (const float*)d_in[12];
    const float* Ws3 = (const float*)d_in[13]; const float* bs3 = (const float*)d_in[14];
    const float* att3 = (const float*)d_in[15];
    const float* Wm4 = (const float*)d_in[16]; const float* bm4 = (const float*)d_in[17];
    const float* Ws4 = (const float*)d_in[18]; const float* bs4 = (const float*)d_in[19];
    const float* att4 = (const float*)d_in[20];
    const float* Wm5 = (const float*)d_in[21]; const float* bm5 = (const float*)d_in[22];
    const float* Ws5 = (const float*)d_in[23]; const float* bs5 = (const float*)d_in[24];
    const float* att5 = (const float*)d_in[25];
    const float* Wc  = (const float*)d_in[26]; const float* bc  = (const float*)d_in[27];

    float *yb, *bufA, *bufB, *bias;
    __nv_bfloat16 *xh, *xl, *wh, *wl;
    cudaGetSymbolAddress((void**)&yb,   g_y);
    cudaGetSymbolAddress((void**)&bufA, g_bufA);
    cudaGetSymbolAddress((void**)&bufB, g_bufB);
    cudaGetSymbolAddress((void**)&xh,   g_xh);
    cudaGetSymbolAddress((void**)&xl,   g_xl);
    cudaGetSymbolAddress((void**)&wh,   g_wh);
    cudaGetSymbolAddress((void**)&wl,   g_wl);
    cudaGetSymbolAddress((void**)&bias, g_bias);

    const int SM128 = 4 * 128 * (128 + 8) * 2 + 1024;   // 140,288 B
    const int SM64  = 4 * 128 * (64 + 8) * 2 + 1024;    //  74,752 B
    cudaFuncSetAttribute(gemm_mma<128, 128>, cudaFuncAttributeMaxDynamicSharedMemorySize, SM128);
    cudaFuncSetAttribute(gemm_mma<128, 64>,  cudaFuncAttributeMaxDynamicSharedMemorySize, SM128);
    cudaFuncSetAttribute(gemm_mma<64, 64>,   cudaFuncAttributeMaxDynamicSharedMemorySize, SM64);

    // weight conversions (cheap)
    convert_w<128, 128><<<(1152 * 128 + 255) / 256, 256>>>(Wm2, bm2, Ws2, bs2,
        wh + 0 * WSLOT, wl + 0 * WSLOT, bias + 0 * 1152);
    convert_w<128, 64><<<(1152 * 128 + 255) / 256, 256>>>(Wm3, bm3, Ws3, bs3,
        wh + 1 * WSLOT, wl + 1 * WSLOT, bias + 1 * 1152);
    convert_w<64, 64><<<(1152 * 64 + 255) / 256, 256>>>(Wm4, bm4, Ws4, bs4,
        wh + 2 * WSLOT, wl + 2 * WSLOT, bias + 2 * 1152);

    const dim3 GG(NUMNODES / 128, 9);

    // Layer 1 (K=1): SIMT outer product
    gemm_l1<<<GG, 256>>>(nodes, Wm1, bm1, Ws1, bs1, att1, yb);
    agg2<128, 8, YSTRIDE, true, true><<<NUMNODES / 8, 256>>>(yb, bufA, xh, xl);

    // Layer 2: mma.sync, K=128, C=128
    gemm_mma<128, 128><<<GG, 256, SM128>>>(xh, xl, wh + 0 * WSLOT, wl + 0 * WSLOT,
                                           bias + 0 * 1152, att2, yb);
    agg2<128, 8, YSTRIDE, true, true><<<NUMNODES / 8, 256>>>(yb, bufB, xh, xl);

    // Layer 3: mma.sync, K=128, C=64
    gemm_mma<128, 64><<<GG, 256, SM128>>>(xh, xl, wh + 1 * WSLOT, wl + 1 * WSLOT,
                                          bias + 1 * 1152, att3, yb);
    agg2<64, 16, YSTRIDE, true, true><<<NUMNODES / 16, 256>>>(yb, bufA, xh, xl);

    // Layer 4: mma.sync, K=64, C=64
    gemm_mma<64, 64><<<GG, 256, SM64>>>(xh, xl, wh + 2 * WSLOT, wl + 2 * WSLOT,
                                        bias + 2 * 1152, att4, yb);
    agg2<64, 16, YSTRIDE, true, false><<<NUMNODES / 16, 256>>>(yb, bufB, nullptr, nullptr);

    // Layer 5 (SIMT, small)
    msg5<<<NUMNODES / 8, 256>>>(bufB, Wm5, bm5, Ws5, bs5, att5, yb);
    agg2<32, 1, 64, false, false><<<NUMNODES / 32, 256>>>(yb, bufA, nullptr, nullptr);

    final_k<<<1, 1024>>>(bufA, Wc, bc, (float*)d_out, out_size);
}

// round 5
// speedup vs baseline: 3.6408x; 1.3613x over previous
#include <cuda_runtime.h>
#include <cuda_bf16.h>
#include <cuda_fp16.h>
#include <cstdint>
#include <cstddef>

#define NUMNODES 32768
#define NCHAIN   1024

// -------- global scratch (no allocations allowed) --------
__device__ __half g_ymsg[(size_t)NUMNODES * 1024];   // 64 MB msg buffer (fp16)
__device__ float  g_yself[(size_t)NUMNODES * 128];   // 16 MB self buffer (fp32)
__device__ float  g_alpha[(size_t)NUMNODES * 16];
__device__ float  g_bufA[(size_t)NUMNODES * 128];
__device__ float  g_bufB[(size_t)NUMNODES * 128];
__device__ __nv_bfloat16 g_xh[(size_t)NUMNODES * 128];
__device__ __nv_bfloat16 g_xl[(size_t)NUMNODES * 128];
#define WSLOT (1152 * 128)
__device__ __nv_bfloat16 g_wh[3 * WSLOT];            // split weights [n][k]
__device__ __nv_bfloat16 g_wl[3 * WSLOT];
__device__ float g_bias[3 * 1152];

// ================= PTX helpers (baseline ISA only) =================
__device__ __forceinline__ uint32_t smem_u32(const void* p) {
    uint32_t a;
    asm("{ .reg .u64 t; cvta.to.shared.u64 t, %1; cvt.u32.u64 %0, t; }" : "=r"(a) : "l"(p));
    return a;
}
__device__ __forceinline__ void cp16(uint32_t dst, const void* src) {
    asm volatile("{ .reg .u64 g; cvta.to.global.u64 g, %1; cp.async.cg.shared.global [%0], [g], 16; }"
        :: "r"(dst), "l"(src) : "memory");
}
__device__ __forceinline__ void cp_commit_wait() {
    asm volatile("cp.async.commit_group;" ::: "memory");
    asm volatile("cp.async.wait_group 0;" ::: "memory");
}
__device__ __forceinline__ void ldm_x4(uint32_t* r, uint32_t addr) {
    asm volatile("ldmatrix.sync.aligned.m8n8.x4.shared.b16 {%0,%1,%2,%3}, [%4];"
        : "=r"(r[0]), "=r"(r[1]), "=r"(r[2]), "=r"(r[3]) : "r"(addr));
}
__device__ __forceinline__ void ldm_x2(uint32_t* r, uint32_t addr) {
    asm volatile("ldmatrix.sync.aligned.m8n8.x2.shared.b16 {%0,%1}, [%2];"
        : "=r"(r[0]), "=r"(r[1]) : "r"(addr));
}
__device__ __forceinline__ void mma_bf16(float* d, const uint32_t* a, const uint32_t* b) {
    asm volatile(
        "mma.sync.aligned.m16n8k16.row.col.f32.bf16.bf16.f32 "
        "{%0,%1,%2,%3}, {%4,%5,%6,%7}, {%8,%9}, {%0,%1,%2,%3};"
        : "+f"(d[0]), "+f"(d[1]), "+f"(d[2]), "+f"(d[3])
        : "r"(a[0]), "r"(a[1]), "r"(a[2]), "r"(a[3]), "r"(b[0]), "r"(b[1]));
}
__device__ __forceinline__ float leaky(float v) { return (v > 0.f) ? v : 0.01f * v; }

// ================= weight split + gather to [n][k] =================
template<int K, int COUT>
__global__ __launch_bounds__(256) void convert_w(
    const float* __restrict__ Wm, const float* __restrict__ bm,
    const float* __restrict__ Ws, const float* __restrict__ bs,
    __nv_bfloat16* __restrict__ wh, __nv_bfloat16* __restrict__ wl,
    float* __restrict__ bias)
{
    const int idx = blockIdx.x * 256 + threadIdx.x;
    if (idx >= 1152 * K) return;
    const int n = idx / K, k = idx % K;
    float v;
    if (n < 1024)             v = Wm[(size_t)k * 1024 + n];
    else if (n < 1024 + COUT) v = Ws[(size_t)k * COUT + (n - 1024)];
    else                      v = 0.f;
    const __nv_bfloat16 h = __float2bfloat16(v);
    wh[idx] = h;
    wl[idx] = __float2bfloat16(v - __bfloat162float(h));
    if (k == 0)
        bias[n] = (n < 1024) ? bm[n] : ((n < 1024 + COUT) ? bs[n - 1024] : 0.f);
}

// ================= fully fused layer 1 =================
// msg1[g] depends only on scalar x[g] -> recompute neighbor msgs on the fly.
// Writes ONLY split-bf16 activations for layer 2.
__global__ __launch_bounds__(256) void fused_l1(
    const float* __restrict__ x,  const float* __restrict__ Wm,
    const float* __restrict__ bm, const float* __restrict__ Ws,
    const float* __restrict__ bs, const float* __restrict__ att,
    __nv_bfloat16* __restrict__ xh, __nv_bfloat16* __restrict__ xl)
{
    __shared__ float wm_s[1024], bm_s[1024], att_s[1024];
    __shared__ float ws_s[128], bs_s[128];
    __shared__ float xs[130];
    __shared__ float alpha_s[1040];
    __shared__ float wl_s[1024], wr_s[1024];

    const int tid = threadIdx.x;
    const int gBase = blockIdx.x * 128;

    for (int i = tid; i < 1024; i += 256) {
        wm_s[i] = Wm[i]; bm_s[i] = bm[i]; att_s[i] = att[i];
    }
    if (tid < 128) { ws_s[tid] = Ws[tid]; bs_s[tid] = bs[tid]; }
    if (tid < 130) {
        int gi = gBase + tid - 1;
        gi = (gi < 0) ? 0 : ((gi > NUMNODES - 1) ? NUMNODES - 1 : gi);
        xs[tid] = x[gi];
    }
    __syncthreads();

    // alpha for 130 halo nodes x 8 heads, warp-cooperative dots
    {
        const int wd = tid >> 5, ln = tid & 31;
        for (int task = wd; task < 1040; task += 8) {
            const int i = task >> 3, h = task & 7;
            const float xv = xs[i];
            const int base = h * 128;
            float a = 0.f;
            #pragma unroll 4
            for (int cc = ln; cc < 128; cc += 32) {
                float t = fmaf(xv, wm_s[base + cc], bm_s[base + cc]);
                t = leaky(t);
                a = fmaf(t, att_s[base + cc], a);
            }
            #pragma unroll
            for (int off = 16; off > 0; off >>= 1)
                a += __shfl_xor_sync(0xffffffffu, a, off);
            if (ln == 0) alpha_s[task] = a;
        }
    }
    __syncthreads();

    // softmax weights (include 1/H)
    for (int idx = tid; idx < 1024; idx += 256) {
        const int n = idx >> 3;
        const int g = gBase + n, nch = g & (NCHAIN - 1);
        float el, er;
        if (nch == 0)               { el = 0.f; er = 1.f; }
        else if (nch == NCHAIN - 1) { el = 1.f; er = 0.f; }
        else {
            const float al = alpha_s[idx];       // node g-1, head h
            const float ar = alpha_s[idx + 16];  // node g+1, head h
            const float mx = fmaxf(al, ar);
            el = expf(al - mx); er = expf(ar - mx);
        }
        const float inv = (1.f / ((el + er) + 1e-16f)) * 0.125f;
        wl_s[idx] = el * inv; wr_s[idx] = er * inv;
    }
    __syncthreads();

    // output: thread = (col, half of nodes); coalesced stores
    const int col = tid & 127;
    const int nStart = (tid >> 7) * 64;
    float wmv[8], bmv[8];
    #pragma unroll
    for (int h = 0; h < 8; h++) { wmv[h] = wm_s[h * 128 + col]; bmv[h] = bm_s[h * 128 + col]; }
    const float wsc = ws_s[col], bsc = bs_s[col];

    for (int n = nStart; n < nStart + 64; n++) {
        const float xL = xs[n], xS = xs[n + 1], xR = xs[n + 2];
        float s = fmaf(xS, wsc, bsc);
        #pragma unroll
        for (int h = 0; h < 8; h++) {
            const float tL = leaky(fmaf(xL, wmv[h], bmv[h]));
            const float tR = leaky(fmaf(xR, wmv[h], bmv[h]));
            s = fmaf(wl_s[n * 8 + h], tL, s);
            s = fmaf(wr_s[n * 8 + h], tR, s);
        }
        s = (s > 0.f) ? s : expm1f(s);           // ELU
        const __nv_bfloat16 hv = __float2bfloat16(s);
        xh[(size_t)(gBase + n) * 128 + col] = hv;
        xl[(size_t)(gBase + n) * 128 + col] = __float2bfloat16(s - __bfloat162float(hv));
    }
}

// ================= mma.sync fused GEMM (layers 2-4) =================
// Tile 64m x 128n, 256 thr (warps 2M x 4N), 2 blocks/SM. fp16 msg out, fp32 self out.
template<int K, int C>
__global__ __launch_bounds__(256, 2) void gemm_mma(
    const __nv_bfloat16* __restrict__ xh, const __nv_bfloat16* __restrict__ xl,
    const __nv_bfloat16* __restrict__ wh, const __nv_bfloat16* __restrict__ wl,
    const float* __restrict__ bias, const float* __restrict__ att,
    __half* __restrict__ ymsg, float* __restrict__ yself)
{
    constexpr int SROW = K + 8;
    extern __shared__ __align__(16) char smem[];
    __nv_bfloat16* sAh = reinterpret_cast<__nv_bfloat16*>(smem);
    __nv_bfloat16* sAl = sAh + 64 * SROW;
    __nv_bfloat16* sBh = sAl + 64 * SROW;
    __nv_bfloat16* sBl = sBh + 128 * SROW;
    float* alpha_s = reinterpret_cast<float*>(sBl + 128 * SROW);   // [4][64]

    const int tid  = threadIdx.x;
    const int lane = tid & 31;
    const int wid  = tid >> 5;
    const int warpM = wid >> 2;          // 0..1
    const int warpN = wid & 3;           // 0..3
    const int g = lane >> 2, t = lane & 3;

    const int mBase = blockIdx.x * 64;
    const int nBase = blockIdx.y * 128;
    const bool isMsg = (nBase < 1024);

    // ---- cp.async cooperative loads ----
    {
        constexpr int VPR = K / 8;                 // uint4 per row
        const uint32_t uAh = smem_u32(sAh), uAl = smem_u32(sAl);
        const uint32_t uBh = smem_u32(sBh), uBl = smem_u32(sBl);
        const uint4* gAh = reinterpret_cast<const uint4*>(xh + (size_t)mBase * K);
        const uint4* gAl = reinterpret_cast<const uint4*>(xl + (size_t)mBase * K);
        const uint4* gBh = reinterpret_cast<const uint4*>(wh + (size_t)nBase * K);
        const uint4* gBl = reinterpret_cast<const uint4*>(wl + (size_t)nBase * K);
        #pragma unroll
        for (int i = 0; i < (64 * VPR) / 256; i++) {
            const int idx = tid + i * 256;
            const int row = idx / VPR, kv = idx % VPR;
            const uint32_t so = (row * (SROW / 8) + kv) * 16;
            cp16(uAh + so, gAh + idx);
            cp16(uAl + so, gAl + idx);
        }
        #pragma unroll
        for (int i = 0; i < (128 * VPR) / 256; i++) {
            const int idx = tid + i * 256;
            const int row = idx / VPR, kv = idx % VPR;
            const uint32_t so = (row * (SROW / 8) + kv) * 16;
            cp16(uBh + so, gBh + idx);
            cp16(uBl + so, gBl + idx);
        }
        cp_commit_wait();
    }
    __syncthreads();

    // ---- MMA mainloop ----
    float acc[2][4][4];
    #pragma unroll
    for (int mi = 0; mi < 2; mi++)
        #pragma unroll
        for (int ni = 0; ni < 4; ni++)
            #pragma unroll
            for (int e = 0; e < 4; e++) acc[mi][ni][e] = 0.f;

    const uint32_t uAh = smem_u32(sAh), uAl = smem_u32(sAl);
    const uint32_t uBh = smem_u32(sBh), uBl = smem_u32(sBl);
    const uint32_t aOfs = ((warpM * 32 + (lane & 15)) * SROW + ((lane >> 4) << 3)) * 2;
    const uint32_t bOfs = ((warpN * 32 + (lane & 7)) * SROW + (((lane >> 3) & 1) << 3)) * 2;

    #pragma unroll
    for (int kc = 0; kc < K / 16; kc++) {
        const uint32_t kByte = kc * 32;
        uint32_t ah[2][4], al[2][4];
        #pragma unroll
        for (int mi = 0; mi < 2; mi++) {
            const uint32_t ro = aOfs + mi * (16 * SROW * 2) + kByte;
            ldm_x4(ah[mi], uAh + ro);
            ldm_x4(al[mi], uAl + ro);
        }
        #pragma unroll
        for (int ni = 0; ni < 4; ni++) {
            const uint32_t ro = bOfs + ni * (8 * SROW * 2) + kByte;
            uint32_t bh[2], bl[2];
            ldm_x2(bh, uBh + ro);
            ldm_x2(bl, uBl + ro);
            #pragma unroll
            for (int mi = 0; mi < 2; mi++) {
                mma_bf16(acc[mi][ni], ah[mi], bh);
                mma_bf16(acc[mi][ni], ah[mi], bl);
                mma_bf16(acc[mi][ni], al[mi], bh);
            }
        }
    }

    // ---- epilogue ----
    float alphaLoc[2][2] = {{0.f, 0.f}, {0.f, 0.f}};

    #pragma unroll
    for (int ni = 0; ni < 4; ni++) {
        const int n0 = nBase + warpN * 32 + ni * 8 + 2 * t;
        const float2 bb = *reinterpret_cast<const float2*>(&bias[n0]);
        float2 aa = make_float2(0.f, 0.f);
        if (isMsg) aa = *reinterpret_cast<const float2*>(&att[n0]);
        #pragma unroll
        for (int mi = 0; mi < 2; mi++) {
            float v0 = acc[mi][ni][0] + bb.x;
            float v1 = acc[mi][ni][1] + bb.y;
            float v2 = acc[mi][ni][2] + bb.x;
            float v3 = acc[mi][ni][3] + bb.y;
            const int row0 = mBase + warpM * 32 + mi * 16 + g;
            if (isMsg) {
                v0 = leaky(v0); v1 = leaky(v1); v2 = leaky(v2); v3 = leaky(v3);
                alphaLoc[mi][0] = fmaf(v0, aa.x, fmaf(v1, aa.y, alphaLoc[mi][0]));
                alphaLoc[mi][1] = fmaf(v2, aa.x, fmaf(v3, aa.y, alphaLoc[mi][1]));
                *reinterpret_cast<__half2*>(ymsg + (size_t)row0 * 1024 + n0) =
                    __floats2half2_rn(v0, v1);
                *reinterpret_cast<__half2*>(ymsg + (size_t)(row0 + 8) * 1024 + n0) =
                    __floats2half2_rn(v2, v3);
            } else {
                const int c = n0 - 1024;
                *reinterpret_cast<float2*>(yself + (size_t)row0 * 128 + c) = make_float2(v0, v1);
                *reinterpret_cast<float2*>(yself + (size_t)(row0 + 8) * 128 + c) = make_float2(v2, v3);
            }
        }
    }

    if (isMsg) {
        #pragma unroll
        for (int mi = 0; mi < 2; mi++)
            #pragma unroll
            for (int rh = 0; rh < 2; rh++) {
                float s = alphaLoc[mi][rh];
                s += __shfl_xor_sync(0xffffffffu, s, 1);
                s += __shfl_xor_sync(0xffffffffu, s, 2);
                alphaLoc[mi][rh] = s;
            }
        if (t == 0) {
            #pragma unroll
            for (int mi = 0; mi < 2; mi++) {
                const int lr = warpM * 32 + mi * 16 + g;
                alpha_s[warpN * 64 + lr]     = alphaLoc[mi][0];
                alpha_s[warpN * 64 + lr + 8] = alphaLoc[mi][1];
            }
        }
    }
    __syncthreads();
    if (isMsg) {
        if (C == 128) {
            if (tid < 64) {
                const float s = alpha_s[tid] + alpha_s[64 + tid] +
                                alpha_s[128 + tid] + alpha_s[192 + tid];
                g_alpha[(size_t)(mBase + tid) * 8 + blockIdx.y] = s;
            }
        } else {
            if (tid < 128) {
                const int r = tid & 63, hh = tid >> 6;
                const float s = alpha_s[hh * 128 + r] + alpha_s[hh * 128 + 64 + r];
                g_alpha[(size_t)(mBase + r) * 16 + blockIdx.y * 2 + hh] = s;
            }
        }
    }
}

// ================= aggregation stencil (fp16 msg + fp32 self) =================
template<int C, int H, bool ELU, bool SPLIT, bool WF32>
__global__ __launch_bounds__(256) void agg2h(
    const __half* __restrict__ ymsg, const float* __restrict__ yself,
    float* __restrict__ xout,
    __nv_bfloat16* __restrict__ xh, __nv_bfloat16* __restrict__ xl)
{
    constexpr int TPN = C / 4;
    constexpr int NPB = 256 / TPN;

    __shared__ float wl_s[NPB * H];
    __shared__ float wr_s[NPB * H];

    const int tid = threadIdx.x;
    const int gBase = blockIdx.x * NPB;

    if (tid < NPB * H) {
        const int node = tid / H, h = tid % H;
        const int g = gBase + node;
        const int nch = g & (NCHAIN - 1);
        float el, er;
        if (nch == 0)               { el = 0.f; er = 1.f; }
        else if (nch == NCHAIN - 1) { el = 1.f; er = 0.f; }
        else {
            const float al = g_alpha[(size_t)(g - 1) * H + h];
            const float ar = g_alpha[(size_t)(g + 1) * H + h];
            const float mx = fmaxf(al, ar);
            el = expf(al - mx); er = expf(ar - mx);
        }
        const float inv = (1.f / ((el + er) + 1e-16f)) * (1.f / H);
        wl_s[tid] = el * inv;
        wr_s[tid] = er * inv;
    }
    __syncthreads();

    const int lane = tid % TPN, node = tid / TPN;
    const int g = gBase + node;
    const int nch = g & (NCHAIN - 1);
    const __half* rowL = ymsg + (size_t)((nch > 0)          ? g - 1 : g) * 1024;
    const __half* rowR = ymsg + (size_t)((nch < NCHAIN - 1) ? g + 1 : g) * 1024;
    const int c4 = lane * 4;

    float4 acc = make_float4(0.f, 0.f, 0.f, 0.f);
    #pragma unroll
    for (int h = 0; h < H; h++) {
        const float wl = wl_s[node * H + h];
        const float wr = wr_s[node * H + h];
        const uint2 uL = *reinterpret_cast<const uint2*>(rowL + h * C + c4);
        const uint2 uR = *reinterpret_cast<const uint2*>(rowR + h * C + c4);
        const float2 l0 = __half22float2(*reinterpret_cast<const __half2*>(&uL.x));
        const float2 l1 = __half22float2(*reinterpret_cast<const __half2*>(&uL.y));
        const float2 r0 = __half22float2(*reinterpret_cast<const __half2*>(&uR.x));
        const float2 r1 = __half22float2(*reinterpret_cast<const __half2*>(&uR.y));
        acc.x = fmaf(wl, l0.x, fmaf(wr, r0.x, acc.x));
        acc.y = fmaf(wl, l0.y, fmaf(wr, r0.y, acc.y));
        acc.z = fmaf(wl, l1.x, fmaf(wr, r1.x, acc.z));
        acc.w = fmaf(wl, l1.y, fmaf(wr, r1.y, acc.w));
    }
    const float4 sv = *reinterpret_cast<const float4*>(yself + (size_t)g * 128 + c4);
    acc.x += sv.x; acc.y += sv.y; acc.z += sv.z; acc.w += sv.w;
    if (ELU) {
        acc.x = (acc.x > 0.f) ? acc.x : expm1f(acc.x);
        acc.y = (acc.y > 0.f) ? acc.y : expm1f(acc.y);
        acc.z = (acc.z > 0.f) ? acc.z : expm1f(acc.z);
        acc.w = (acc.w > 0.f) ? acc.w : expm1f(acc.w);
    }
    if (WF32)
        *reinterpret_cast<float4*>(xout + (size_t)g * C + c4) = acc;
    if (SPLIT) {
        const float vv[4] = {acc.x, acc.y, acc.z, acc.w};
        __nv_bfloat16 hv[4], lv[4];
        #pragma unroll
        for (int e = 0; e < 4; e++) {
            hv[e] = __float2bfloat16(vv[e]);
            lv[e] = __float2bfloat16(vv[e] - __bfloat162float(hv[e]));
        }
        *reinterpret_cast<uint2*>(xh + (size_t)g * C + c4) = *reinterpret_cast<uint2*>(hv);
        *reinterpret_cast<uint2*>(xl + (size_t)g * C + c4) = *reinterpret_cast<uint2*>(lv);
    }
}

// ================= layer 5 msg+self (fp32, small) =================
__global__ __launch_bounds__(256) void msg5(
    const float* __restrict__ x,  const float* __restrict__ Wm,
    const float* __restrict__ bm, const float* __restrict__ Ws,
    const float* __restrict__ bs, const float* __restrict__ att,
    float* __restrict__ y)
{
    __shared__ float wm_s[64 * 32];
    __shared__ float ws_s[64 * 32];
    __shared__ float x_s[8 * 64];

    const int tid = threadIdx.x;
    const int n = tid >> 5, o = tid & 31;
    const int gBase = blockIdx.x * 8;

    for (int i = tid; i < 64 * 32; i += 256) { wm_s[i] = Wm[i]; ws_s[i] = Ws[i]; }
    for (int i = tid; i < 8 * 64; i += 256)  x_s[i] = x[(size_t)gBase * 64 + i];
    __syncthreads();

    float am = __ldg(&bm[o]);
    float as = __ldg(&bs[o]);
    #pragma unroll
    for (int k = 0; k < 64; k++) {
        const float xv = x_s[n * 64 + k];
        am = fmaf(xv, wm_s[k * 32 + o], am);
        as = fmaf(xv, ws_s[k * 32 + o], as);
    }
    am = leaky(am);
    const int gg = gBase + n;
    y[(size_t)gg * 64 + o]      = am;
    y[(size_t)gg * 64 + 32 + o] = as;

    float a = am * __ldg(&att[o]);
    #pragma unroll
    for (int off = 16; off > 0; off >>= 1)
        a += __shfl_xor_sync(0xffffffffu, a, off);
    if (o == 0) g_alpha[gg] = a;
}

// fp32 agg for layer 5 (C=32, H=1, stride 64)
__global__ __launch_bounds__(256) void agg5(
    const float* __restrict__ y, float* __restrict__ xout)
{
    constexpr int TPN = 8, NPB = 32;
    __shared__ float wl_s[NPB], wr_s[NPB];
    const int tid = threadIdx.x;
    const int gBase = blockIdx.x * NPB;

    if (tid < NPB) {
        const int g = gBase + tid;
        const int nch = g & (NCHAIN - 1);
        float el, er;
        if (nch == 0)               { el = 0.f; er = 1.f; }
        else if (nch == NCHAIN - 1) { el = 1.f; er = 0.f; }
        else {
            const float al = g_alpha[(size_t)(g - 1)];
            const float ar = g_alpha[(size_t)(g + 1)];
            const float mx = fmaxf(al, ar);
            el = expf(al - mx); er = expf(ar - mx);
        }
        const float inv = 1.f / ((el + er) + 1e-16f);
        wl_s[tid] = el * inv;
        wr_s[tid] = er * inv;
    }
    __syncthreads();

    const int lane = tid % TPN, node = tid / TPN;
    const int g = gBase + node;
    const int nch = g & (NCHAIN - 1);
    const float* rowL = y + (size_t)((nch > 0)          ? g - 1 : g) * 64;
    const float* rowR = y + (size_t)((nch < NCHAIN - 1) ? g + 1 : g) * 64;
    const int c4 = lane * 4;
    const float wl = wl_s[node], wr = wr_s[node];
    const float4 mL = *reinterpret_cast<const float4*>(rowL + c4);
    const float4 mR = *reinterpret_cast<const float4*>(rowR + c4);
    const float4 sv = *reinterpret_cast<const float4*>(y + (size_t)g * 64 + 32 + c4);
    float4 acc;
    acc.x = fmaf(wl, mL.x, fmaf(wr, mR.x, sv.x));
    acc.y = fmaf(wl, mL.y, fmaf(wr, mR.y, sv.y));
    acc.z = fmaf(wl, mL.z, fmaf(wr, mR.z, sv.z));
    acc.w = fmaf(wl, mL.w, fmaf(wr, mR.w, sv.w));
    *reinterpret_cast<float4*>(xout + (size_t)g * 32 + c4) = acc;
}

// ================= readout =================
__global__ __launch_bounds__(1024) void final_k(
    const float* __restrict__ x5, const float* __restrict__ Wc,
    const float* __restrict__ bc, float* __restrict__ out, int out_size)
{
    const int tid = threadIdx.x;
    const int b = tid >> 5;
    const int c = tid & 31;
    const float v = x5[((size_t)b * NCHAIN + (NCHAIN - 1)) * 32 + c];
    if (32 + tid < out_size) out[32 + tid] = v;
    float p = v * __ldg(&Wc[c]);
    #pragma unroll
    for (int off = 16; off > 0; off >>= 1)
        p += __shfl_down_sync(0xffffffffu, p, off);
    if (c == 0 && b < out_size) out[b] = p + __ldg(&bc[0]);
}

// ================= launch =================
extern "C" void kernel_launch(void* const* d_in, const int* in_sizes, int n_in,
                              void* d_out, int out_size)
{
    const float* nodes = (const float*)d_in[0];
    const float* Wm1 = (const float*)d_in[1];  const float* bm1 = (const float*)d_in[2];
    const float* Ws1 = (const float*)d_in[3];  const float* bs1 = (const float*)d_in[4];
    const float* att1 = (const float*)d_in[5];
    const float* Wm2 = (const float*)d_in[6];  const float* bm2 = (const float*)d_in[7];
    const float* Ws2 = (const float*)d_in[8];  const float* bs2 = (const float*)d_in[9];
    const float* att2 = (const float*)d_in[10];
    const float* Wm3 = (const float*)d_in[11]; const float* bm3 = (const float*)d_in[12];
    const float* Ws3 = (const float*)d_in[13]; const float* bs3 = (const float*)d_in[14];
    const float* att3 = (const float*)d_in[15];
    const float* Wm4 = (const float*)d_in[16]; const float* bm4 = (const float*)d_in[17];
    const float* Ws4 = (const float*)d_in[18]; const float* bs4 = (const float*)d_in[19];
    const float* att4 = (const float*)d_in[20];
    const float* Wm5 = (const float*)d_in[21]; const float* bm5 = (const float*)d_in[22];
    const float* Ws5 = (const float*)d_in[23]; const float* bs5 = (const float*)d_in[24];
    const float* att5 = (const float*)d_in[25];
    const float* Wc  = (const float*)d_in[26]; const float* bc  = (const float*)d_in[27];

    __half* ymsg; float *yself, *bufA, *bufB, *bias;
    __nv_bfloat16 *xh, *xl, *wh, *wl;
    cudaGetSymbolAddress((void**)&ymsg,  g_ymsg);
    cudaGetSymbolAddress((void**)&yself, g_yself);
    cudaGetSymbolAddress((void**)&bufA,  g_bufA);
    cudaGetSymbolAddress((void**)&bufB,  g_bufB);
    cudaGetSymbolAddress((void**)&xh,    g_xh);
    cudaGetSymbolAddress((void**)&xl,    g_xl);
    cudaGetSymbolAddress((void**)&wh,    g_wh);
    cudaGetSymbolAddress((void**)&wl,    g_wl);
    cudaGetSymbolAddress((void**)&bias,  g_bias);

    const int SM128 = (2 * 64 * 136 + 2 * 128 * 136) * 2 + 1024;   // 105,472 B
    const int SM64  = (2 * 64 * 72  + 2 * 128 * 72)  * 2 + 1024;   //  56,320 B
    cudaFuncSetAttribute(gemm_mma<128, 128>, cudaFuncAttributeMaxDynamicSharedMemorySize, SM128);
    cudaFuncSetAttribute(gemm_mma<128, 64>,  cudaFuncAttributeMaxDynamicSharedMemorySize, SM128);
    cudaFuncSetAttribute(gemm_mma<64, 64>,   cudaFuncAttributeMaxDynamicSharedMemorySize, SM64);

    // weight conversions (cheap)
    convert_w<128, 128><<<(1152 * 128 + 255) / 256, 256>>>(Wm2, bm2, Ws2, bs2,
        wh + 0 * WSLOT, wl + 0 * WSLOT, bias + 0 * 1152);
    convert_w<128, 64><<<(1152 * 128 + 255) / 256, 256>>>(Wm3, bm3, Ws3, bs3,
        wh + 1 * WSLOT, wl + 1 * WSLOT, bias + 1 * 1152);
    convert_w<64, 64><<<(1152 * 64 + 255) / 256, 256>>>(Wm4, bm4, Ws4, bs4,
        wh + 2 * WSLOT, wl + 2 * WSLOT, bias + 2 * 1152);

    // Layer 1: fully fused (no intermediate buffer)
    fused_l1<<<NUMNODES / 128, 256>>>(nodes, Wm1, bm1, Ws1, bs1, att1, xh, xl);

    const dim3 GG(NUMNODES / 64, 9);

    // Layer 2: K=128, C=128
    gemm_mma<128, 128><<<GG, 256, SM128>>>(xh, xl, wh + 0 * WSLOT, wl + 0 * WSLOT,
                                           bias + 0 * 1152, att2, ymsg, yself);
    agg2h<128, 8, true, true, false><<<NUMNODES / 8, 256>>>(ymsg, yself, nullptr, xh, xl);

    // Layer 3: K=128, C=64
    gemm_mma<128, 64><<<GG, 256, SM128>>>(xh, xl, wh + 1 * WSLOT, wl + 1 * WSLOT,
                                          bias + 1 * 1152, att3, ymsg, yself);
    agg2h<64, 16, true, true, false><<<NUMNODES / 16, 256>>>(ymsg, yself, nullptr, xh, xl);

    // Layer 4: K=64, C=64
    gemm_mma<64, 64><<<GG, 256, SM64>>>(xh, xl, wh + 2 * WSLOT, wl + 2 * WSLOT,
                                        bias + 2 * 1152, att4, ymsg, yself);
    agg2h<64, 16, true, false, true><<<NUMNODES / 16, 256>>>(ymsg, yself, bufB, nullptr, nullptr);

    // Layer 5 (small, fp32) — reuse yself as stride-64 scratch
    msg5<<<NUMNODES / 8, 256>>>(bufB, Wm5, bm5, Ws5, bs5, att5, yself);
    agg5<<<NUMNODES / 32, 256>>>(yself, bufA);

    final_k<<<1, 1024>>>(bufA, Wc, bc, (float*)d_out, out_size);
}

// round 6
// speedup vs baseline: 3.8503x; 1.0575x over previous
#include <cuda_runtime.h>
#include <cuda_bf16.h>
#include <cuda_fp16.h>
#include <cstdint>
#include <cstddef>

#define NUMNODES 32768
#define NCHAIN   1024

// -------- global scratch (no allocations allowed) --------
__device__ __half g_ymsg[(size_t)NUMNODES * 1024];   // 64 MB msg buffer (fp16)
__device__ float  g_yself[(size_t)NUMNODES * 128];   // 16 MB self buffer (fp32)
__device__ float  g_alpha[(size_t)NUMNODES * 16];
__device__ float  g_bufA[(size_t)NUMNODES * 128];
__device__ float  g_bufB[(size_t)NUMNODES * 128];
__device__ __nv_bfloat16 g_xh[(size_t)NUMNODES * 128];
__device__ __nv_bfloat16 g_xl[(size_t)NUMNODES * 128];
#define WSLOT (1152 * 128)
__device__ __nv_bfloat16 g_wh[3 * WSLOT];            // split weights [n][k]
__device__ __nv_bfloat16 g_wl[3 * WSLOT];
__device__ float g_bias[3 * 1152];

// ================= PTX helpers (baseline ISA only) =================
__device__ __forceinline__ uint32_t smem_u32(const void* p) {
    uint32_t a;
    asm("{ .reg .u64 t; cvta.to.shared.u64 t, %1; cvt.u32.u64 %0, t; }" : "=r"(a) : "l"(p));
    return a;
}
__device__ __forceinline__ void cp16(uint32_t dst, const void* src) {
    asm volatile("{ .reg .u64 g; cvta.to.global.u64 g, %1; cp.async.cg.shared.global [%0], [g], 16; }"
        :: "r"(dst), "l"(src) : "memory");
}
__device__ __forceinline__ void cp_commit_wait() {
    asm volatile("cp.async.commit_group;" ::: "memory");
    asm volatile("cp.async.wait_group 0;" ::: "memory");
}
__device__ __forceinline__ void ldm_x4(uint32_t* r, uint32_t addr) {
    asm volatile("ldmatrix.sync.aligned.m8n8.x4.shared.b16 {%0,%1,%2,%3}, [%4];"
        : "=r"(r[0]), "=r"(r[1]), "=r"(r[2]), "=r"(r[3]) : "r"(addr));
}
__device__ __forceinline__ void ldm_x2(uint32_t* r, uint32_t addr) {
    asm volatile("ldmatrix.sync.aligned.m8n8.x2.shared.b16 {%0,%1}, [%2];"
        : "=r"(r[0]), "=r"(r[1]) : "r"(addr));
}
__device__ __forceinline__ void mma_bf16(float* d, const uint32_t* a, const uint32_t* b) {
    asm volatile(
        "mma.sync.aligned.m16n8k16.row.col.f32.bf16.bf16.f32 "
        "{%0,%1,%2,%3}, {%4,%5,%6,%7}, {%8,%9}, {%0,%1,%2,%3};"
        : "+f"(d[0]), "+f"(d[1]), "+f"(d[2]), "+f"(d[3])
        : "r"(a[0]), "r"(a[1]), "r"(a[2]), "r"(a[3]), "r"(b[0]), "r"(b[1]));
}
__device__ __forceinline__ float leaky(float v) { return (v > 0.f) ? v : 0.01f * v; }

// ================= combined weight split (all 3 MMA layers) =================
__global__ __launch_bounds__(256) void convert_w_all(
    const float* __restrict__ Wm2, const float* __restrict__ bm2,
    const float* __restrict__ Ws2, const float* __restrict__ bs2,
    const float* __restrict__ Wm3, const float* __restrict__ bm3,
    const float* __restrict__ Ws3, const float* __restrict__ bs3,
    const float* __restrict__ Wm4, const float* __restrict__ bm4,
    const float* __restrict__ Ws4, const float* __restrict__ bs4,
    __nv_bfloat16* __restrict__ wh, __nv_bfloat16* __restrict__ wl,
    float* __restrict__ bias)
{
    int idx = blockIdx.x * 256 + threadIdx.x;
    int layer, K, COUT;
    const float *Wm, *bm, *Ws, *bs;
    if (idx < 1152 * 128) {
        layer = 0; K = 128; COUT = 128; Wm = Wm2; bm = bm2; Ws = Ws2; bs = bs2;
    } else if (idx < 2 * 1152 * 128) {
        idx -= 1152 * 128;
        layer = 1; K = 128; COUT = 64; Wm = Wm3; bm = bm3; Ws = Ws3; bs = bs3;
    } else if (idx < 2 * 1152 * 128 + 1152 * 64) {
        idx -= 2 * 1152 * 128;
        layer = 2; K = 64; COUT = 64; Wm = Wm4; bm = bm4; Ws = Ws4; bs = bs4;
    } else return;

    const int n = idx / K, k = idx % K;
    float v;
    if (n < 1024)             v = Wm[(size_t)k * 1024 + n];
    else if (n < 1024 + COUT) v = Ws[(size_t)k * COUT + (n - 1024)];
    else                      v = 0.f;
    const __nv_bfloat16 h = __float2bfloat16(v);
    wh[(size_t)layer * WSLOT + idx] = h;
    wl[(size_t)layer * WSLOT + idx] = __float2bfloat16(v - __bfloat162float(h));
    if (k == 0)
        bias[layer * 1152 + n] = (n < 1024) ? bm[n] : ((n < 1024 + COUT) ? bs[n - 1024] : 0.f);
}

// ================= layer 1: alpha (per-node per-head logits) =================
// warp w -> head w; lane l -> node. Weights broadcast from smem.
__global__ __launch_bounds__(256) void alpha1(
    const float* __restrict__ x, const float* __restrict__ Wm,
    const float* __restrict__ bm, const float* __restrict__ att)
{
    __shared__ float wm_s[1024], bm_s[1024], att_s[1024];
    const int tid = threadIdx.x;
    for (int i = tid; i < 1024; i += 256) {
        wm_s[i] = Wm[i]; bm_s[i] = bm[i]; att_s[i] = att[i];
    }
    __syncthreads();

    const int w = tid >> 5, l = tid & 31;
    const int g = blockIdx.x * 32 + l;
    const float xv = x[g];
    const int base = w * 128;
    float a = 0.f;
    #pragma unroll 8
    for (int c = 0; c < 128; c++) {
        const float t = leaky(fmaf(xv, wm_s[base + c], bm_s[base + c]));
        a = fmaf(t, att_s[base + c], a);
    }
    g_alpha[(size_t)g * 8 + w] = a;
}

// ================= layer 1: output (agg + self + ELU + split) =================
__global__ __launch_bounds__(256) void out1(
    const float* __restrict__ x,  const float* __restrict__ Wm,
    const float* __restrict__ bm, const float* __restrict__ Ws,
    const float* __restrict__ bs,
    __nv_bfloat16* __restrict__ xh, __nv_bfloat16* __restrict__ xl)
{
    constexpr int NPB = 32;
    __shared__ float wm_s[1024], bm_s[1024];
    __shared__ float ws_s[128], bs_s[128];
    __shared__ float wgt[NPB][16];       // wl[8] | wr[8]
    __shared__ float xs[NPB + 2];

    const int tid = threadIdx.x;
    const int gBase = blockIdx.x * NPB;

    for (int i = tid; i < 1024; i += 256) { wm_s[i] = Wm[i]; bm_s[i] = bm[i]; }
    if (tid < 128) { ws_s[tid] = Ws[tid]; bs_s[tid] = bs[tid]; }
    if (tid < NPB + 2) {
        int gi = gBase + tid - 1;
        gi = (gi < 0) ? 0 : ((gi > NUMNODES - 1) ? NUMNODES - 1 : gi);
        xs[tid] = x[gi];
    }
    // softmax weights: 32 nodes x 8 heads = 256 tasks, one per thread
    {
        const int node = tid >> 3, h = tid & 7;
        const int g = gBase + node;
        const int nch = g & (NCHAIN - 1);
        float el, er;
        if (nch == 0)               { el = 0.f; er = 1.f; }
        else if (nch == NCHAIN - 1) { el = 1.f; er = 0.f; }
        else {
            const float al = g_alpha[(size_t)(g - 1) * 8 + h];
            const float ar = g_alpha[(size_t)(g + 1) * 8 + h];
            const float mx = fmaxf(al, ar);
            el = expf(al - mx); er = expf(ar - mx);
        }
        const float inv = (1.f / ((el + er) + 1e-16f)) * 0.125f;
        wgt[node][h]     = el * inv;
        wgt[node][8 + h] = er * inv;
    }
    __syncthreads();

    const int col = tid & 127;
    float wmv[8], bmv[8];
    #pragma unroll
    for (int h = 0; h < 8; h++) { wmv[h] = wm_s[h * 128 + col]; bmv[h] = bm_s[h * 128 + col]; }
    const float wsc = ws_s[col], bsc = bs_s[col];

    for (int n = (tid >> 7); n < NPB; n += 2) {
        const int g = gBase + n;
        const float xL = xs[n], xS = xs[n + 1], xR = xs[n + 2];
        float s = fmaf(xS, wsc, bsc);
        #pragma unroll
        for (int h = 0; h < 8; h++) {
            const float tL = leaky(fmaf(xL, wmv[h], bmv[h]));
            const float tR = leaky(fmaf(xR, wmv[h], bmv[h]));
            s = fmaf(wgt[n][h], tL, s);
            s = fmaf(wgt[n][8 + h], tR, s);
        }
        s = (s > 0.f) ? s : expm1f(s);           // ELU
        const __nv_bfloat16 hv = __float2bfloat16(s);
        xh[(size_t)g * 128 + col] = hv;
        xl[(size_t)g * 128 + col] = __float2bfloat16(s - __bfloat162float(hv));
    }
}

// ================= mma.sync fused GEMM (layers 2-4) =================
// Tile 64m x 128n, 256 thr (warps 2M x 4N), 2 blocks/SM. fp16 msg out, fp32 self out.
template<int K, int C>
__global__ __launch_bounds__(256, 2) void gemm_mma(
    const __nv_bfloat16* __restrict__ xh, const __nv_bfloat16* __restrict__ xl,
    const __nv_bfloat16* __restrict__ wh, const __nv_bfloat16* __restrict__ wl,
    const float* __restrict__ bias, const float* __restrict__ att,
    __half* __restrict__ ymsg, float* __restrict__ yself)
{
    constexpr int SROW = K + 8;
    extern __shared__ __align__(16) char smem[];
    __nv_bfloat16* sAh = reinterpret_cast<__nv_bfloat16*>(smem);
    __nv_bfloat16* sAl = sAh + 64 * SROW;
    __nv_bfloat16* sBh = sAl + 64 * SROW;
    __nv_bfloat16* sBl = sBh + 128 * SROW;
    float* alpha_s = reinterpret_cast<float*>(sBl + 128 * SROW);   // [4][64]

    const int tid  = threadIdx.x;
    const int lane = tid & 31;
    const int wid  = tid >> 5;
    const int warpM = wid >> 2;          // 0..1
    const int warpN = wid & 3;           // 0..3
    const int g = lane >> 2, t = lane & 3;

    const int mBase = blockIdx.x * 64;
    const int nBase = blockIdx.y * 128;
    const bool isMsg = (nBase < 1024);

    // ---- cp.async cooperative loads ----
    {
        constexpr int VPR = K / 8;                 // uint4 per row
        const uint32_t uAh = smem_u32(sAh), uAl = smem_u32(sAl);
        const uint32_t uBh = smem_u32(sBh), uBl = smem_u32(sBl);
        const uint4* gAh = reinterpret_cast<const uint4*>(xh + (size_t)mBase * K);
        const uint4* gAl = reinterpret_cast<const uint4*>(xl + (size_t)mBase * K);
        const uint4* gBh = reinterpret_cast<const uint4*>(wh + (size_t)nBase * K);
        const uint4* gBl = reinterpret_cast<const uint4*>(wl + (size_t)nBase * K);
        #pragma unroll
        for (int i = 0; i < (64 * VPR) / 256; i++) {
            const int idx = tid + i * 256;
            const int row = idx / VPR, kv = idx % VPR;
            const uint32_t so = (row * (SROW / 8) + kv) * 16;
            cp16(uAh + so, gAh + idx);
            cp16(uAl + so, gAl + idx);
        }
        #pragma unroll
        for (int i = 0; i < (128 * VPR) / 256; i++) {
            const int idx = tid + i * 256;
            const int row = idx / VPR, kv = idx % VPR;
            const uint32_t so = (row * (SROW / 8) + kv) * 16;
            cp16(uBh + so, gBh + idx);
            cp16(uBl + so, gBl + idx);
        }
        cp_commit_wait();
    }
    __syncthreads();

    // ---- MMA mainloop ----
    float acc[2][4][4];
    #pragma unroll
    for (int mi = 0; mi < 2; mi++)
        #pragma unroll
        for (int ni = 0; ni < 4; ni++)
            #pragma unroll
            for (int e = 0; e < 4; e++) acc[mi][ni][e] = 0.f;

    const uint32_t uAh = smem_u32(sAh), uAl = smem_u32(sAl);
    const uint32_t uBh = smem_u32(sBh), uBl = smem_u32(sBl);
    const uint32_t aOfs = ((warpM * 32 + (lane & 15)) * SROW + ((lane >> 4) << 3)) * 2;
    const uint32_t bOfs = ((warpN * 32 + (lane & 7)) * SROW + (((lane >> 3) & 1) << 3)) * 2;

    #pragma unroll
    for (int kc = 0; kc < K / 16; kc++) {
        const uint32_t kByte = kc * 32;
        uint32_t ah[2][4], al[2][4];
        #pragma unroll
        for (int mi = 0; mi < 2; mi++) {
            const uint32_t ro = aOfs + mi * (16 * SROW * 2) + kByte;
            ldm_x4(ah[mi], uAh + ro);
            ldm_x4(al[mi], uAl + ro);
        }
        #pragma unroll
        for (int ni = 0; ni < 4; ni++) {
            const uint32_t ro = bOfs + ni * (8 * SROW * 2) + kByte;
            uint32_t bh[2], bl[2];
            ldm_x2(bh, uBh + ro);
            ldm_x2(bl, uBl + ro);
            #pragma unroll
            for (int mi = 0; mi < 2; mi++) {
                mma_bf16(acc[mi][ni], ah[mi], bh);
                mma_bf16(acc[mi][ni], ah[mi], bl);
                mma_bf16(acc[mi][ni], al[mi], bh);
            }
        }
    }

    // ---- epilogue ----
    float alphaLoc[2][2] = {{0.f, 0.f}, {0.f, 0.f}};

    #pragma unroll
    for (int ni = 0; ni < 4; ni++) {
        const int n0 = nBase + warpN * 32 + ni * 8 + 2 * t;
        const float2 bb = *reinterpret_cast<const float2*>(&bias[n0]);
        float2 aa = make_float2(0.f, 0.f);
        if (isMsg) aa = *reinterpret_cast<const float2*>(&att[n0]);
        #pragma unroll
        for (int mi = 0; mi < 2; mi++) {
            float v0 = acc[mi][ni][0] + bb.x;
            float v1 = acc[mi][ni][1] + bb.y;
            float v2 = acc[mi][ni][2] + bb.x;
            float v3 = acc[mi][ni][3] + bb.y;
            const int row0 = mBase + warpM * 32 + mi * 16 + g;
            if (isMsg) {
                v0 = leaky(v0); v1 = leaky(v1); v2 = leaky(v2); v3 = leaky(v3);
                alphaLoc[mi][0] = fmaf(v0, aa.x, fmaf(v1, aa.y, alphaLoc[mi][0]));
                alphaLoc[mi][1] = fmaf(v2, aa.x, fmaf(v3, aa.y, alphaLoc[mi][1]));
                *reinterpret_cast<__half2*>(ymsg + (size_t)row0 * 1024 + n0) =
                    __floats2half2_rn(v0, v1);
                *reinterpret_cast<__half2*>(ymsg + (size_t)(row0 + 8) * 1024 + n0) =
                    __floats2half2_rn(v2, v3);
            } else {
                const int c = n0 - 1024;
                *reinterpret_cast<float2*>(yself + (size_t)row0 * 128 + c) = make_float2(v0, v1);
                *reinterpret_cast<float2*>(yself + (size_t)(row0 + 8) * 128 + c) = make_float2(v2, v3);
            }
        }
    }

    if (isMsg) {
        #pragma unroll
        for (int mi = 0; mi < 2; mi++)
            #pragma unroll
            for (int rh = 0; rh < 2; rh++) {
                float s = alphaLoc[mi][rh];
                s += __shfl_xor_sync(0xffffffffu, s, 1);
                s += __shfl_xor_sync(0xffffffffu, s, 2);
                alphaLoc[mi][rh] = s;
            }
        if (t == 0) {
            #pragma unroll
            for (int mi = 0; mi < 2; mi++) {
                const int lr = warpM * 32 + mi * 16 + g;
                alpha_s[warpN * 64 + lr]     = alphaLoc[mi][0];
                alpha_s[warpN * 64 + lr + 8] = alphaLoc[mi][1];
            }
        }
    }
    __syncthreads();
    if (isMsg) {
        if (C == 128) {
            if (tid < 64) {
                const float s = alpha_s[tid] + alpha_s[64 + tid] +
                                alpha_s[128 + tid] + alpha_s[192 + tid];
                g_alpha[(size_t)(mBase + tid) * 8 + blockIdx.y] = s;
            }
        } else {
            if (tid < 128) {
                const int r = tid & 63, hh = tid >> 6;
                const float s = alpha_s[hh * 128 + r] + alpha_s[hh * 128 + 64 + r];
                g_alpha[(size_t)(mBase + r) * 16 + blockIdx.y * 2 + hh] = s;
            }
        }
    }
}

// ================= aggregation stencil (fp16 msg + fp32 self) =================
template<int C, int H, bool ELU, bool SPLIT, bool WF32>
__global__ __launch_bounds__(256) void agg2h(
    const __half* __restrict__ ymsg, const float* __restrict__ yself,
    float* __restrict__ xout,
    __nv_bfloat16* __restrict__ xh, __nv_bfloat16* __restrict__ xl)
{
    constexpr int TPN = C / 4;
    constexpr int NPB = 256 / TPN;

    __shared__ float wl_s[NPB * H];
    __shared__ float wr_s[NPB * H];

    const int tid = threadIdx.x;
    const int gBase = blockIdx.x * NPB;

    if (tid < NPB * H) {
        const int node = tid / H, h = tid % H;
        const int g = gBase + node;
        const int nch = g & (NCHAIN - 1);
        float el, er;
        if (nch == 0)               { el = 0.f; er = 1.f; }
        else if (nch == NCHAIN - 1) { el = 1.f; er = 0.f; }
        else {
            const float al = g_alpha[(size_t)(g - 1) * H + h];
            const float ar = g_alpha[(size_t)(g + 1) * H + h];
            const float mx = fmaxf(al, ar);
            el = expf(al - mx); er = expf(ar - mx);
        }
        const float inv = (1.f / ((el + er) + 1e-16f)) * (1.f / H);
        wl_s[tid] = el * inv;
        wr_s[tid] = er * inv;
    }
    __syncthreads();

    const int lane = tid % TPN, node = tid / TPN;
    const int g = gBase + node;
    const int nch = g & (NCHAIN - 1);
    const __half* rowL = ymsg + (size_t)((nch > 0)          ? g - 1 : g) * 1024;
    const __half* rowR = ymsg + (size_t)((nch < NCHAIN - 1) ? g + 1 : g) * 1024;
    const int c4 = lane * 4;

    float4 acc = make_float4(0.f, 0.f, 0.f, 0.f);
    #pragma unroll
    for (int h = 0; h < H; h++) {
        const float wl = wl_s[node * H + h];
        const float wr = wr_s[node * H + h];
        const uint2 uL = *reinterpret_cast<const uint2*>(rowL + h * C + c4);
        const uint2 uR = *reinterpret_cast<const uint2*>(rowR + h * C + c4);
        const float2 l0 = __half22float2(*reinterpret_cast<const __half2*>(&uL.x));
        const float2 l1 = __half22float2(*reinterpret_cast<const __half2*>(&uL.y));
        const float2 r0 = __half22float2(*reinterpret_cast<const __half2*>(&uR.x));
        const float2 r1 = __half22float2(*reinterpret_cast<const __half2*>(&uR.y));
        acc.x = fmaf(wl, l0.x, fmaf(wr, r0.x, acc.x));
        acc.y = fmaf(wl, l0.y, fmaf(wr, r0.y, acc.y));
        acc.z = fmaf(wl, l1.x, fmaf(wr, r1.x, acc.z));
        acc.w = fmaf(wl, l1.y, fmaf(wr, r1.y, acc.w));
    }
    const float4 sv = *reinterpret_cast<const float4*>(yself + (size_t)g * 128 + c4);
    acc.x += sv.x; acc.y += sv.y; acc.z += sv.z; acc.w += sv.w;
    if (ELU) {
        acc.x = (acc.x > 0.f) ? acc.x : expm1f(acc.x);
        acc.y = (acc.y > 0.f) ? acc.y : expm1f(acc.y);
        acc.z = (acc.z > 0.f) ? acc.z : expm1f(acc.z);
        acc.w = (acc.w > 0.f) ? acc.w : expm1f(acc.w);
    }
    if (WF32)
        *reinterpret_cast<float4*>(xout + (size_t)g * C + c4) = acc;
    if (SPLIT) {
        const float vv[4] = {acc.x, acc.y, acc.z, acc.w};
        __nv_bfloat16 hv[4], lv[4];
        #pragma unroll
        for (int e = 0; e < 4; e++) {
            hv[e] = __float2bfloat16(vv[e]);
            lv[e] = __float2bfloat16(vv[e] - __bfloat162float(hv[e]));
        }
        *reinterpret_cast<uint2*>(xh + (size_t)g * C + c4) = *reinterpret_cast<uint2*>(hv);
        *reinterpret_cast<uint2*>(xl + (size_t)g * C + c4) = *reinterpret_cast<uint2*>(lv);
    }
}

// ================= layer 5 msg+self (fp32, small) =================
__global__ __launch_bounds__(256) void msg5(
    const float* __restrict__ x,  const float* __restrict__ Wm,
    const float* __restrict__ bm, const float* __restrict__ Ws,
    const float* __restrict__ bs, const float* __restrict__ att,
    float* __restrict__ y)
{
    __shared__ float wm_s[64 * 32];
    __shared__ float ws_s[64 * 32];
    __shared__ float x_s[8 * 64];

    const int tid = threadIdx.x;
    const int n = tid >> 5, o = tid & 31;
    const int gBase = blockIdx.x * 8;

    for (int i = tid; i < 64 * 32; i += 256) { wm_s[i] = Wm[i]; ws_s[i] = Ws[i]; }
    for (int i = tid; i < 8 * 64; i += 256)  x_s[i] = x[(size_t)gBase * 64 + i];
    __syncthreads();

    float am = __ldg(&bm[o]);
    float as = __ldg(&bs[o]);
    #pragma unroll
    for (int k = 0; k < 64; k++) {
        const float xv = x_s[n * 64 + k];
        am = fmaf(xv, wm_s[k * 32 + o], am);
        as = fmaf(xv, ws_s[k * 32 + o], as);
    }
    am = leaky(am);
    const int gg = gBase + n;
    y[(size_t)gg * 64 + o]      = am;
    y[(size_t)gg * 64 + 32 + o] = as;

    float a = am * __ldg(&att[o]);
    #pragma unroll
    for (int off = 16; off > 0; off >>= 1)
        a += __shfl_xor_sync(0xffffffffu, a, off);
    if (o == 0) g_alpha[gg] = a;
}

// fp32 agg for layer 5 (C=32, H=1, stride 64)
__global__ __launch_bounds__(256) void agg5(
    const float* __restrict__ y, float* __restrict__ xout)
{
    constexpr int TPN = 8, NPB = 32;
    __shared__ float wl_s[NPB], wr_s[NPB];
    const int tid = threadIdx.x;
    const int gBase = blockIdx.x * NPB;

    if (tid < NPB) {
        const int g = gBase + tid;
        const int nch = g & (NCHAIN - 1);
        float el, er;
        if (nch == 0)               { el = 0.f; er = 1.f; }
        else if (nch == NCHAIN - 1) { el = 1.f; er = 0.f; }
        else {
            const float al = g_alpha[(size_t)(g - 1)];
            const float ar = g_alpha[(size_t)(g + 1)];
            const float mx = fmaxf(al, ar);
            el = expf(al - mx); er = expf(ar - mx);
        }
        const float inv = 1.f / ((el + er) + 1e-16f);
        wl_s[tid] = el * inv;
        wr_s[tid] = er * inv;
    }
    __syncthreads();

    const int lane = tid % TPN, node = tid / TPN;
    const int g = gBase + node;
    const int nch = g & (NCHAIN - 1);
    const float* rowL = y + (size_t)((nch > 0)          ? g - 1 : g) * 64;
    const float* rowR = y + (size_t)((nch < NCHAIN - 1) ? g + 1 : g) * 64;
    const int c4 = lane * 4;
    const float wl = wl_s[node], wr = wr_s[node];
    const float4 mL = *reinterpret_cast<const float4*>(rowL + c4);
    const float4 mR = *reinterpret_cast<const float4*>(rowR + c4);
    const float4 sv = *reinterpret_cast<const float4*>(y + (size_t)g * 64 + 32 + c4);
    float4 acc;
    acc.x = fmaf(wl, mL.x, fmaf(wr, mR.x, sv.x));
    acc.y = fmaf(wl, mL.y, fmaf(wr, mR.y, sv.y));
    acc.z = fmaf(wl, mL.z, fmaf(wr, mR.z, sv.z));
    acc.w = fmaf(wl, mL.w, fmaf(wr, mR.w, sv.w));
    *reinterpret_cast<float4*>(xout + (size_t)g * 32 + c4) = acc;
}

// ================= readout =================
__global__ __launch_bounds__(1024) void final_k(
    const float* __restrict__ x5, const float* __restrict__ Wc,
    const float* __restrict__ bc, float* __restrict__ out, int out_size)
{
    const int tid = threadIdx.x;
    const int b = tid >> 5;
    const int c = tid & 31;
    const float v = x5[((size_t)b * NCHAIN + (NCHAIN - 1)) * 32 + c];
    if (32 + tid < out_size) out[32 + tid] = v;
    float p = v * __ldg(&Wc[c]);
    #pragma unroll
    for (int off = 16; off > 0; off >>= 1)
        p += __shfl_down_sync(0xffffffffu, p, off);
    if (c == 0 && b < out_size) out[b] = p + __ldg(&bc[0]);
}

// ================= launch =================
extern "C" void kernel_launch(void* const* d_in, const int* in_sizes, int n_in,
                              void* d_out, int out_size)
{
    const float* nodes = (const float*)d_in[0];
    const float* Wm1 = (const float*)d_in[1];  const float* bm1 = (const float*)d_in[2];
    const float* Ws1 = (const float*)d_in[3];  const float* bs1 = (const float*)d_in[4];
    const float* att1 = (const float*)d_in[5];
    const float* Wm2 = (const float*)d_in[6];  const float* bm2 = (const float*)d_in[7];
    const float* Ws2 = (const float*)d_in[8];  const float* bs2 = (const float*)d_in[9];
    const float* att2 = (const float*)d_in[10];
    const float* Wm3 = (const float*)d_in[11]; const float* bm3 = (const float*)d_in[12];
    const float* Ws3 = (const float*)d_in[13]; const float* bs3 = (const float*)d_in[14];
    const float* att3 = (const float*)d_in[15];
    const float* Wm4 = (const float*)d_in[16]; const float* bm4 = (const float*)d_in[17];
    const float* Ws4 = (const float*)d_in[18]; const float* bs4 = (const float*)d_in[19];
    const float* att4 = (const float*)d_in[20];
    const float* Wm5 = (const float*)d_in[21]; const float* bm5 = (const float*)d_in[22];
    const float* Ws5 = (const float*)d_in[23]; const float* bs5 = (const float*)d_in[24];
    const float* att5 = (const float*)d_in[25];
    const float* Wc  = (const float*)d_in[26]; const float* bc  = (const float*)d_in[27];

    __half* ymsg; float *yself, *bufA, *bufB, *bias;
    __nv_bfloat16 *xh, *xl, *wh, *wl;
    cudaGetSymbolAddress((void**)&ymsg,  g_ymsg);
    cudaGetSymbolAddress((void**)&yself, g_yself);
    cudaGetSymbolAddress((void**)&bufA,  g_bufA);
    cudaGetSymbolAddress((void**)&bufB,  g_bufB);
    cudaGetSymbolAddress((void**)&xh,    g_xh);
    cudaGetSymbolAddress((void**)&xl,    g_xl);
    cudaGetSymbolAddress((void**)&wh,    g_wh);
    cudaGetSymbolAddress((void**)&wl,    g_wl);
    cudaGetSymbolAddress((void**)&bias,  g_bias);

    const int SM128 = (2 * 64 * 136 + 2 * 128 * 136) * 2 + 1024;   // 105,472 B
    const int SM64  = (2 * 64 * 72  + 2 * 128 * 72)  * 2 + 1024;   //  56,320 B
    cudaFuncSetAttribute(gemm_mma<128, 128>, cudaFuncAttributeMaxDynamicSharedMemorySize, SM128);
    cudaFuncSetAttribute(gemm_mma<128, 64>,  cudaFuncAttributeMaxDynamicSharedMemorySize, SM128);
    cudaFuncSetAttribute(gemm_mma<64, 64>,   cudaFuncAttributeMaxDynamicSharedMemorySize, SM64);

    // combined weight conversion (one launch)
    const int WTOT = 2 * 1152 * 128 + 1152 * 64;
    convert_w_all<<<(WTOT + 255) / 256, 256>>>(Wm2, bm2, Ws2, bs2,
                                               Wm3, bm3, Ws3, bs3,
                                               Wm4, bm4, Ws4, bs4, wh, wl, bias);

    // Layer 1: high-parallelism alpha + output
    alpha1<<<NUMNODES / 32, 256>>>(nodes, Wm1, bm1, att1);
    out1<<<NUMNODES / 32, 256>>>(nodes, Wm1, bm1, Ws1, bs1, xh, xl);

    const dim3 GG(NUMNODES / 64, 9);

    // Layer 2: K=128, C=128
    gemm_mma<128, 128><<<GG, 256, SM128>>>(xh, xl, wh + 0 * WSLOT, wl + 0 * WSLOT,
                                           bias + 0 * 1152, att2, ymsg, yself);
    agg2h<128, 8, true, true, false><<<NUMNODES / 8, 256>>>(ymsg, yself, nullptr, xh, xl);

    // Layer 3: K=128, C=64
    gemm_mma<128, 64><<<GG, 256, SM128>>>(xh, xl, wh + 1 * WSLOT, wl + 1 * WSLOT,
                                          bias + 1 * 1152, att3, ymsg, yself);
    agg2h<64, 16, true, true, false><<<NUMNODES / 16, 256>>>(ymsg, yself, nullptr, xh, xl);

    // Layer 4: K=64, C=64
    gemm_mma<64, 64><<<GG, 256, SM64>>>(xh, xl, wh + 2 * WSLOT, wl + 2 * WSLOT,
                                        bias + 2 * 1152, att4, ymsg, yself);
    agg2h<64, 16, true, false, true><<<NUMNODES / 16, 256>>>(ymsg, yself, bufB, nullptr, nullptr);

    // Layer 5 (small, fp32) — reuse yself as stride-64 scratch
    msg5<<<NUMNODES / 8, 256>>>(bufB, Wm5, bm5, Ws5, bs5, att5, yself);
    agg5<<<NUMNODES / 32, 256>>>(yself, bufA);

    final_k<<<1, 1024>>>(bufA, Wc, bc, (float*)d_out, out_size);
}

// round 7
// speedup vs baseline: 4.7910x; 1.2443x over previous
#include <cuda_runtime.h>
#include <cuda_fp16.h>
#include <cstdint>
#include <cstddef>

#define NUMNODES 32768
#define NCHAIN   1024

// -------- global scratch (no allocations allowed) --------
__device__ __half g_ymsg[(size_t)NUMNODES * 1024];   // 64 MB msg buffer (fp16)
__device__ float  g_yself[(size_t)NUMNODES * 128];   // 16 MB self buffer (fp32)
__device__ float  g_alpha[(size_t)NUMNODES * 16];
__device__ float  g_bufA[(size_t)NUMNODES * 128];
__device__ float  g_bufB[(size_t)NUMNODES * 128];
__device__ __half g_xh[(size_t)NUMNODES * 128];      // split activations (fp16)
__device__ __half g_xl[(size_t)NUMNODES * 128];
#define WSLOT (1152 * 128)
__device__ __half g_w16[3 * WSLOT];                  // single fp16 weights [n][k]
__device__ float g_bias[3 * 1152];

// ================= PTX helpers (baseline ISA only) =================
__device__ __forceinline__ uint32_t smem_u32(const void* p) {
    uint32_t a;
    asm("{ .reg .u64 t; cvta.to.shared.u64 t, %1; cvt.u32.u64 %0, t; }" : "=r"(a) : "l"(p));
    return a;
}
__device__ __forceinline__ void cp16(uint32_t dst, const void* src) {
    asm volatile("{ .reg .u64 g; cvta.to.global.u64 g, %1; cp.async.cg.shared.global [%0], [g], 16; }"
        :: "r"(dst), "l"(src) : "memory");
}
__device__ __forceinline__ void cp_commit_wait() {
    asm volatile("cp.async.commit_group;" ::: "memory");
    asm volatile("cp.async.wait_group 0;" ::: "memory");
}
__device__ __forceinline__ void ldm_x4(uint32_t* r, uint32_t addr) {
    asm volatile("ldmatrix.sync.aligned.m8n8.x4.shared.b16 {%0,%1,%2,%3}, [%4];"
        : "=r"(r[0]), "=r"(r[1]), "=r"(r[2]), "=r"(r[3]) : "r"(addr));
}
__device__ __forceinline__ void ldm_x2(uint32_t* r, uint32_t addr) {
    asm volatile("ldmatrix.sync.aligned.m8n8.x2.shared.b16 {%0,%1}, [%2];"
        : "=r"(r[0]), "=r"(r[1]) : "r"(addr));
}
__device__ __forceinline__ void mma_f16(float* d, const uint32_t* a, const uint32_t* b) {
    asm volatile(
        "mma.sync.aligned.m16n8k16.row.col.f32.f16.f16.f32 "
        "{%0,%1,%2,%3}, {%4,%5,%6,%7}, {%8,%9}, {%0,%1,%2,%3};"
        : "+f"(d[0]), "+f"(d[1]), "+f"(d[2]), "+f"(d[3])
        : "r"(a[0]), "r"(a[1]), "r"(a[2]), "r"(a[3]), "r"(b[0]), "r"(b[1]));
}
__device__ __forceinline__ float leaky(float v) { return (v > 0.f) ? v : 0.01f * v; }

// ================= combined weight convert (all 3 MMA layers) =================
__global__ __launch_bounds__(256) void convert_w_all(
    const float* __restrict__ Wm2, const float* __restrict__ bm2,
    const float* __restrict__ Ws2, const float* __restrict__ bs2,
    const float* __restrict__ Wm3, const float* __restrict__ bm3,
    const float* __restrict__ Ws3, const float* __restrict__ bs3,
    const float* __restrict__ Wm4, const float* __restrict__ bm4,
    const float* __restrict__ Ws4, const float* __restrict__ bs4,
    __half* __restrict__ w16, float* __restrict__ bias)
{
    int idx = blockIdx.x * 256 + threadIdx.x;
    int layer, K, COUT;
    const float *Wm, *bm, *Ws, *bs;
    if (idx < 1152 * 128) {
        layer = 0; K = 128; COUT = 128; Wm = Wm2; bm = bm2; Ws = Ws2; bs = bs2;
    } else if (idx < 2 * 1152 * 128) {
        idx -= 1152 * 128;
        layer = 1; K = 128; COUT = 64; Wm = Wm3; bm = bm3; Ws = Ws3; bs = bs3;
    } else if (idx < 2 * 1152 * 128 + 1152 * 64) {
        idx -= 2 * 1152 * 128;
        layer = 2; K = 64; COUT = 64; Wm = Wm4; bm = bm4; Ws = Ws4; bs = bs4;
    } else return;

    const int n = idx / K, k = idx % K;
    float v;
    if (n < 1024)             v = Wm[(size_t)k * 1024 + n];
    else if (n < 1024 + COUT) v = Ws[(size_t)k * COUT + (n - 1024)];
    else                      v = 0.f;
    w16[(size_t)layer * WSLOT + idx] = __float2half(v);
    if (k == 0)
        bias[layer * 1152 + n] = (n < 1024) ? bm[n] : ((n < 1024 + COUT) ? bs[n - 1024] : 0.f);
}

// ================= layer 1: alpha =================
__global__ __launch_bounds__(256) void alpha1(
    const float* __restrict__ x, const float* __restrict__ Wm,
    const float* __restrict__ bm, const float* __restrict__ att)
{
    __shared__ float wm_s[1024], bm_s[1024], att_s[1024];
    const int tid = threadIdx.x;
    for (int i = tid; i < 1024; i += 256) {
        wm_s[i] = Wm[i]; bm_s[i] = bm[i]; att_s[i] = att[i];
    }
    __syncthreads();

    const int w = tid >> 5, l = tid & 31;
    const int g = blockIdx.x * 32 + l;
    const float xv = x[g];
    const int base = w * 128;
    float a = 0.f;
    #pragma unroll 8
    for (int c = 0; c < 128; c++) {
        const float t = leaky(fmaf(xv, wm_s[base + c], bm_s[base + c]));
        a = fmaf(t, att_s[base + c], a);
    }
    g_alpha[(size_t)g * 8 + w] = a;
}

// ================= layer 1: output (agg + self + ELU + split fp16) =================
__global__ __launch_bounds__(256) void out1(
    const float* __restrict__ x,  const float* __restrict__ Wm,
    const float* __restrict__ bm, const float* __restrict__ Ws,
    const float* __restrict__ bs,
    __half* __restrict__ xh, __half* __restrict__ xl)
{
    constexpr int NPB = 32;
    __shared__ float wm_s[1024], bm_s[1024];
    __shared__ float ws_s[128], bs_s[128];
    __shared__ float wgt[NPB][16];
    __shared__ float xs[NPB + 2];

    const int tid = threadIdx.x;
    const int gBase = blockIdx.x * NPB;

    for (int i = tid; i < 1024; i += 256) { wm_s[i] = Wm[i]; bm_s[i] = bm[i]; }
    if (tid < 128) { ws_s[tid] = Ws[tid]; bs_s[tid] = bs[tid]; }
    if (tid < NPB + 2) {
        int gi = gBase + tid - 1;
        gi = (gi < 0) ? 0 : ((gi > NUMNODES - 1) ? NUMNODES - 1 : gi);
        xs[tid] = x[gi];
    }
    {
        const int node = tid >> 3, h = tid & 7;
        const int g = gBase + node;
        const int nch = g & (NCHAIN - 1);
        float el, er;
        if (nch == 0)               { el = 0.f; er = 1.f; }
        else if (nch == NCHAIN - 1) { el = 1.f; er = 0.f; }
        else {
            const float al = g_alpha[(size_t)(g - 1) * 8 + h];
            const float ar = g_alpha[(size_t)(g + 1) * 8 + h];
            const float mx = fmaxf(al, ar);
            el = expf(al - mx); er = expf(ar - mx);
        }
        const float inv = (1.f / ((el + er) + 1e-16f)) * 0.125f;
        wgt[node][h]     = el * inv;
        wgt[node][8 + h] = er * inv;
    }
    __syncthreads();

    const int col = tid & 127;
    float wmv[8], bmv[8];
    #pragma unroll
    for (int h = 0; h < 8; h++) { wmv[h] = wm_s[h * 128 + col]; bmv[h] = bm_s[h * 128 + col]; }
    const float wsc = ws_s[col], bsc = bs_s[col];

    for (int n = (tid >> 7); n < NPB; n += 2) {
        const int g = gBase + n;
        const float xL = xs[n], xS = xs[n + 1], xR = xs[n + 2];
        float s = fmaf(xS, wsc, bsc);
        #pragma unroll
        for (int h = 0; h < 8; h++) {
            const float tL = leaky(fmaf(xL, wmv[h], bmv[h]));
            const float tR = leaky(fmaf(xR, wmv[h], bmv[h]));
            s = fmaf(wgt[n][h], tL, s);
            s = fmaf(wgt[n][8 + h], tR, s);
        }
        s = (s > 0.f) ? s : expm1f(s);           // ELU
        const __half hv = __float2half(s);
        xh[(size_t)g * 128 + col] = hv;
        xl[(size_t)g * 128 + col] = __float2half(s - __half2float(hv));
    }
}

// ================= mma.sync fused GEMM (layers 2-4), 2-pass exact-A =================
// D = xh*w + xl*w (= x*w with x split in fp16; weight quantization 2^-11 only).
// Tile 64m x 128n, 256 thr (warps 2M x 4N), 3 blocks/SM target.
template<int K, int C>
__global__ __launch_bounds__(256, 3) void gemm_mma(
    const __half* __restrict__ xh, const __half* __restrict__ xl,
    const __half* __restrict__ w16,
    const float* __restrict__ bias, const float* __restrict__ att,
    __half* __restrict__ ymsg, float* __restrict__ yself)
{
    constexpr int SROW = K + 8;
    extern __shared__ __align__(16) char smem[];
    __half* sAh = reinterpret_cast<__half*>(smem);
    __half* sAl = sAh + 64 * SROW;
    __half* sB  = sAl + 64 * SROW;
    float* alpha_s = reinterpret_cast<float*>(sB + 128 * SROW);   // [4][64]

    const int tid  = threadIdx.x;
    const int lane = tid & 31;
    const int wid  = tid >> 5;
    const int warpM = wid >> 2;          // 0..1
    const int warpN = wid & 3;           // 0..3
    const int g = lane >> 2, t = lane & 3;

    const int mBase = blockIdx.x * 64;
    const int nBase = blockIdx.y * 128;
    const bool isMsg = (nBase < 1024);

    // ---- cp.async cooperative loads ----
    {
        constexpr int VPR = K / 8;
        const uint32_t uAh = smem_u32(sAh), uAl = smem_u32(sAl);
        const uint32_t uB = smem_u32(sB);
        const uint4* gAh = reinterpret_cast<const uint4*>(xh + (size_t)mBase * K);
        const uint4* gAl = reinterpret_cast<const uint4*>(xl + (size_t)mBase * K);
        const uint4* gB  = reinterpret_cast<const uint4*>(w16 + (size_t)nBase * K);
        #pragma unroll
        for (int i = 0; i < (64 * VPR) / 256; i++) {
            const int idx = tid + i * 256;
            const int row = idx / VPR, kv = idx % VPR;
            const uint32_t so = (row * (SROW / 8) + kv) * 16;
            cp16(uAh + so, gAh + idx);
            cp16(uAl + so, gAl + idx);
        }
        #pragma unroll
        for (int i = 0; i < (128 * VPR) / 256; i++) {
            const int idx = tid + i * 256;
            const int row = idx / VPR, kv = idx % VPR;
            const uint32_t so = (row * (SROW / 8) + kv) * 16;
            cp16(uB + so, gB + idx);
        }
        cp_commit_wait();
    }
    __syncthreads();

    // ---- MMA mainloop ----
    float acc[2][4][4];
    #pragma unroll
    for (int mi = 0; mi < 2; mi++)
        #pragma unroll
        for (int ni = 0; ni < 4; ni++)
            #pragma unroll
            for (int e = 0; e < 4; e++) acc[mi][ni][e] = 0.f;

    const uint32_t uAh = smem_u32(sAh), uAl = smem_u32(sAl);
    const uint32_t uB = smem_u32(sB);
    const uint32_t aOfs = ((warpM * 32 + (lane & 15)) * SROW + ((lane >> 4) << 3)) * 2;
    const uint32_t bOfs = ((warpN * 32 + (lane & 7)) * SROW + (((lane >> 3) & 1) << 3)) * 2;

    #pragma unroll
    for (int kc = 0; kc < K / 16; kc++) {
        const uint32_t kByte = kc * 32;
        uint32_t ah[2][4], al[2][4];
        #pragma unroll
        for (int mi = 0; mi < 2; mi++) {
            const uint32_t ro = aOfs + mi * (16 * SROW * 2) + kByte;
            ldm_x4(ah[mi], uAh + ro);
            ldm_x4(al[mi], uAl + ro);
        }
        #pragma unroll
        for (int ni = 0; ni < 4; ni++) {
            const uint32_t ro = bOfs + ni * (8 * SROW * 2) + kByte;
            uint32_t bw[2];
            ldm_x2(bw, uB + ro);
            #pragma unroll
            for (int mi = 0; mi < 2; mi++) {
                mma_f16(acc[mi][ni], ah[mi], bw);
                mma_f16(acc[mi][ni], al[mi], bw);
            }
        }
    }

    // ---- epilogue ----
    float alphaLoc[2][2] = {{0.f, 0.f}, {0.f, 0.f}};

    #pragma unroll
    for (int ni = 0; ni < 4; ni++) {
        const int n0 = nBase + warpN * 32 + ni * 8 + 2 * t;
        const float2 bb = *reinterpret_cast<const float2*>(&bias[n0]);
        float2 aa = make_float2(0.f, 0.f);
        if (isMsg) aa = *reinterpret_cast<const float2*>(&att[n0]);
        #pragma unroll
        for (int mi = 0; mi < 2; mi++) {
            float v0 = acc[mi][ni][0] + bb.x;
            float v1 = acc[mi][ni][1] + bb.y;
            float v2 = acc[mi][ni][2] + bb.x;
            float v3 = acc[mi][ni][3] + bb.y;
            const int row0 = mBase + warpM * 32 + mi * 16 + g;
            if (isMsg) {
                v0 = leaky(v0); v1 = leaky(v1); v2 = leaky(v2); v3 = leaky(v3);
                alphaLoc[mi][0] = fmaf(v0, aa.x, fmaf(v1, aa.y, alphaLoc[mi][0]));
                alphaLoc[mi][1] = fmaf(v2, aa.x, fmaf(v3, aa.y, alphaLoc[mi][1]));
                *reinterpret_cast<__half2*>(ymsg + (size_t)row0 * 1024 + n0) =
                    __floats2half2_rn(v0, v1);
                *reinterpret_cast<__half2*>(ymsg + (size_t)(row0 + 8) * 1024 + n0) =
                    __floats2half2_rn(v2, v3);
            } else {
                const int c = n0 - 1024;
                *reinterpret_cast<float2*>(yself + (size_t)row0 * 128 + c) = make_float2(v0, v1);
                *reinterpret_cast<float2*>(yself + (size_t)(row0 + 8) * 128 + c) = make_float2(v2, v3);
            }
        }
    }

    if (isMsg) {
        #pragma unroll
        for (int mi = 0; mi < 2; mi++)
            #pragma unroll
            for (int rh = 0; rh < 2; rh++) {
                float s = alphaLoc[mi][rh];
                s += __shfl_xor_sync(0xffffffffu, s, 1);
                s += __shfl_xor_sync(0xffffffffu, s, 2);
                alphaLoc[mi][rh] = s;
            }
        if (t == 0) {
            #pragma unroll
            for (int mi = 0; mi < 2; mi++) {
                const int lr = warpM * 32 + mi * 16 + g;
                alpha_s[warpN * 64 + lr]     = alphaLoc[mi][0];
                alpha_s[warpN * 64 + lr + 8] = alphaLoc[mi][1];
            }
        }
    }
    __syncthreads();
    if (isMsg) {
        if (C == 128) {
            if (tid < 64) {
                const float s = alpha_s[tid] + alpha_s[64 + tid] +
                                alpha_s[128 + tid] + alpha_s[192 + tid];
                g_alpha[(size_t)(mBase + tid) * 8 + blockIdx.y] = s;
            }
        } else {
            if (tid < 128) {
                const int r = tid & 63, hh = tid >> 6;
                const float s = alpha_s[hh * 128 + r] + alpha_s[hh * 128 + 64 + r];
                g_alpha[(size_t)(mBase + r) * 16 + blockIdx.y * 2 + hh] = s;
            }
        }
    }
}

// ================= aggregation stencil (fp16 msg + fp32 self) =================
template<int C, int H, bool ELU, bool SPLIT, bool WF32>
__global__ __launch_bounds__(256) void agg2h(
    const __half* __restrict__ ymsg, const float* __restrict__ yself,
    float* __restrict__ xout,
    __half* __restrict__ xh, __half* __restrict__ xl)
{
    constexpr int TPN = C / 4;
    constexpr int NPB = 256 / TPN;

    __shared__ float wl_s[NPB * H];
    __shared__ float wr_s[NPB * H];

    const int tid = threadIdx.x;
    const int gBase = blockIdx.x * NPB;

    if (tid < NPB * H) {
        const int node = tid / H, h = tid % H;
        const int g = gBase + node;
        const int nch = g & (NCHAIN - 1);
        float el, er;
        if (nch == 0)               { el = 0.f; er = 1.f; }
        else if (nch == NCHAIN - 1) { el = 1.f; er = 0.f; }
        else {
            const float al = g_alpha[(size_t)(g - 1) * H + h];
            const float ar = g_alpha[(size_t)(g + 1) * H + h];
            const float mx = fmaxf(al, ar);
            el = expf(al - mx); er = expf(ar - mx);
        }
        const float inv = (1.f / ((el + er) + 1e-16f)) * (1.f / H);
        wl_s[tid] = el * inv;
        wr_s[tid] = er * inv;
    }
    __syncthreads();

    const int lane = tid % TPN, node = tid / TPN;
    const int g = gBase + node;
    const int nch = g & (NCHAIN - 1);
    const __half* rowL = ymsg + (size_t)((nch > 0)          ? g - 1 : g) * 1024;
    const __half* rowR = ymsg + (size_t)((nch < NCHAIN - 1) ? g + 1 : g) * 1024;
    const int c4 = lane * 4;

    float4 acc = make_float4(0.f, 0.f, 0.f, 0.f);
    #pragma unroll
    for (int h = 0; h < H; h++) {
        const float wl = wl_s[node * H + h];
        const float wr = wr_s[node * H + h];
        const uint2 uL = *reinterpret_cast<const uint2*>(rowL + h * C + c4);
        const uint2 uR = *reinterpret_cast<const uint2*>(rowR + h * C + c4);
        const float2 l0 = __half22float2(*reinterpret_cast<const __half2*>(&uL.x));
        const float2 l1 = __half22float2(*reinterpret_cast<const __half2*>(&uL.y));
        const float2 r0 = __half22float2(*reinterpret_cast<const __half2*>(&uR.x));
        const float2 r1 = __half22float2(*reinterpret_cast<const __half2*>(&uR.y));
        acc.x = fmaf(wl, l0.x, fmaf(wr, r0.x, acc.x));
        acc.y = fmaf(wl, l0.y, fmaf(wr, r0.y, acc.y));
        acc.z = fmaf(wl, l1.x, fmaf(wr, r1.x, acc.z));
        acc.w = fmaf(wl, l1.y, fmaf(wr, r1.y, acc.w));
    }
    const float4 sv = *reinterpret_cast<const float4*>(yself + (size_t)g * 128 + c4);
    acc.x += sv.x; acc.y += sv.y; acc.z += sv.z; acc.w += sv.w;
    if (ELU) {
        acc.x = (acc.x > 0.f) ? acc.x : expm1f(acc.x);
        acc.y = (acc.y > 0.f) ? acc.y : expm1f(acc.y);
        acc.z = (acc.z > 0.f) ? acc.z : expm1f(acc.z);
        acc.w = (acc.w > 0.f) ? acc.w : expm1f(acc.w);
    }
    if (WF32)
        *reinterpret_cast<float4*>(xout + (size_t)g * C + c4) = acc;
    if (SPLIT) {
        const float vv[4] = {acc.x, acc.y, acc.z, acc.w};
        __half hv[4], lv[4];
        #pragma unroll
        for (int e = 0; e < 4; e++) {
            hv[e] = __float2half(vv[e]);
            lv[e] = __float2half(vv[e] - __half2float(hv[e]));
        }
        *reinterpret_cast<uint2*>(xh + (size_t)g * C + c4) = *reinterpret_cast<uint2*>(hv);
        *reinterpret_cast<uint2*>(xl + (size_t)g * C + c4) = *reinterpret_cast<uint2*>(lv);
    }
}

// ================= layer 5 msg+self (fp32, small) =================
__global__ __launch_bounds__(256) void msg5(
    const float* __restrict__ x,  const float* __restrict__ Wm,
    const float* __restrict__ bm, const float* __restrict__ Ws,
    const float* __restrict__ bs, const float* __restrict__ att,
    float* __restrict__ y)
{
    __shared__ float wm_s[64 * 32];
    __shared__ float ws_s[64 * 32];
    __shared__ float x_s[8 * 64];

    const int tid = threadIdx.x;
    const int n = tid >> 5, o = tid & 31;
    const int gBase = blockIdx.x * 8;

    for (int i = tid; i < 64 * 32; i += 256) { wm_s[i] = Wm[i]; ws_s[i] = Ws[i]; }
    for (int i = tid; i < 8 * 64; i += 256)  x_s[i] = x[(size_t)gBase * 64 + i];
    __syncthreads();

    float am = __ldg(&bm[o]);
    float as = __ldg(&bs[o]);
    #pragma unroll
    for (int k = 0; k < 64; k++) {
        const float xv = x_s[n * 64 + k];
        am = fmaf(xv, wm_s[k * 32 + o], am);
        as = fmaf(xv, ws_s[k * 32 + o], as);
    }
    am = leaky(am);
    const int gg = gBase + n;
    y[(size_t)gg * 64 + o]      = am;
    y[(size_t)gg * 64 + 32 + o] = as;

    float a = am * __ldg(&att[o]);
    #pragma unroll
    for (int off = 16; off > 0; off >>= 1)
        a += __shfl_xor_sync(0xffffffffu, a, off);
    if (o == 0) g_alpha[gg] = a;
}

// fp32 agg for layer 5 (C=32, H=1, stride 64)
__global__ __launch_bounds__(256) void agg5(
    const float* __restrict__ y, float* __restrict__ xout)
{
    constexpr int TPN = 8, NPB = 32;
    __shared__ float wl_s[NPB], wr_s[NPB];
    const int tid = threadIdx.x;
    const int gBase = blockIdx.x * NPB;

    if (tid < NPB) {
        const int g = gBase + tid;
        const int nch = g & (NCHAIN - 1);
        float el, er;
        if (nch == 0)               { el = 0.f; er = 1.f; }
        else if (nch == NCHAIN - 1) { el = 1.f; er = 0.f; }
        else {
            const float al = g_alpha[(size_t)(g - 1)];
            const float ar = g_alpha[(size_t)(g + 1)];
            const float mx = fmaxf(al, ar);
            el = expf(al - mx); er = expf(ar - mx);
        }
        const float inv = 1.f / ((el + er) + 1e-16f);
        wl_s[tid] = el * inv;
        wr_s[tid] = er * inv;
    }
    __syncthreads();

    const int lane = tid % TPN, node = tid / TPN;
    const int g = gBase + node;
    const int nch = g & (NCHAIN - 1);
    const float* rowL = y + (size_t)((nch > 0)          ? g - 1 : g) * 64;
    const float* rowR = y + (size_t)((nch < NCHAIN - 1) ? g + 1 : g) * 64;
    const int c4 = lane * 4;
    const float wl = wl_s[node], wr = wr_s[node];
    const float4 mL = *reinterpret_cast<const float4*>(rowL + c4);
    const float4 mR = *reinterpret_cast<const float4*>(rowR + c4);
    const float4 sv = *reinterpret_cast<const float4*>(y + (size_t)g * 64 + 32 + c4);
    float4 acc;
    acc.x = fmaf(wl, mL.x, fmaf(wr, mR.x, sv.x));
    acc.y = fmaf(wl, mL.y, fmaf(wr, mR.y, sv.y));
    acc.z = fmaf(wl, mL.z, fmaf(wr, mR.z, sv.z));
    acc.w = fmaf(wl, mL.w, fmaf(wr, mR.w, sv.w));
    *reinterpret_cast<float4*>(xout + (size_t)g * 32 + c4) = acc;
}

// ================= readout =================
__global__ __launch_bounds__(1024) void final_k(
    const float* __restrict__ x5, const float* __restrict__ Wc,
    const float* __restrict__ bc, float* __restrict__ out, int out_size)
{
    const int tid = threadIdx.x;
    const int b = tid >> 5;
    const int c = tid & 31;
    const float v = x5[((size_t)b * NCHAIN + (NCHAIN - 1)) * 32 + c];
    if (32 + tid < out_size) out[32 + tid] = v;
    float p = v * __ldg(&Wc[c]);
    #pragma unroll
    for (int off = 16; off > 0; off >>= 1)
        p += __shfl_down_sync(0xffffffffu, p, off);
    if (c == 0 && b < out_size) out[b] = p + __ldg(&bc[0]);
}

// ================= launch =================
extern "C" void kernel_launch(void* const* d_in, const int* in_sizes, int n_in,
                              void* d_out, int out_size)
{
    const float* nodes = (const float*)d_in[0];
    const float* Wm1 = (const float*)d_in[1];  const float* bm1 = (const float*)d_in[2];
    const float* Ws1 = (const float*)d_in[3];  const float* bs1 = (const float*)d_in[4];
    const float* att1 = (const float*)d_in[5];
    const float* Wm2 = (const float*)d_in[6];  const float* bm2 = (const float*)d_in[7];
    const float* Ws2 = (const float*)d_in[8];  const float* bs2 = (const float*)d_in[9];
    const float* att2 = (const float*)d_in[10];
    const float* Wm3 = (const float*)d_in[11]; const float* bm3 = (const float*)d_in[12];
    const float* Ws3 = (const float*)d_in[13]; const float* bs3 = (const float*)d_in[14];
    const float* att3 = (const float*)d_in[15];
    const float* Wm4 = (const float*)d_in[16]; const float* bm4 = (const float*)d_in[17];
    const float* Ws4 = (const float*)d_in[18]; const float* bs4 = (const float*)d_in[19];
    const float* att4 = (const float*)d_in[20];
    const float* Wm5 = (const float*)d_in[21]; const float* bm5 = (const float*)d_in[22];
    const float* Ws5 = (const float*)d_in[23]; const float* bs5 = (const float*)d_in[24];
    const float* att5 = (const float*)d_in[25];
    const float* Wc  = (const float*)d_in[26]; const float* bc  = (const float*)d_in[27];

    __half *ymsg, *xh, *xl, *w16;
    float *yself, *bufA, *bufB, *bias;
    cudaGetSymbolAddress((void**)&ymsg,  g_ymsg);
    cudaGetSymbolAddress((void**)&yself, g_yself);
    cudaGetSymbolAddress((void**)&bufA,  g_bufA);
    cudaGetSymbolAddress((void**)&bufB,  g_bufB);
    cudaGetSymbolAddress((void**)&xh,    g_xh);
    cudaGetSymbolAddress((void**)&xl,    g_xl);
    cudaGetSymbolAddress((void**)&w16,   g_w16);
    cudaGetSymbolAddress((void**)&bias,  g_bias);

    const int SM128 = (2 * 64 * 136 + 128 * 136) * 2 + 1024;   // 70,656 B
    const int SM64  = (2 * 64 * 72  + 128 * 72)  * 2 + 1024;   // 37,888 B
    cudaFuncSetAttribute(gemm_mma<128, 128>, cudaFuncAttributeMaxDynamicSharedMemorySize, SM128);
    cudaFuncSetAttribute(gemm_mma<128, 64>,  cudaFuncAttributeMaxDynamicSharedMemorySize, SM128);
    cudaFuncSetAttribute(gemm_mma<64, 64>,   cudaFuncAttributeMaxDynamicSharedMemorySize, SM64);

    const int WTOT = 2 * 1152 * 128 + 1152 * 64;
    convert_w_all<<<(WTOT + 255) / 256, 256>>>(Wm2, bm2, Ws2, bs2,
                                               Wm3, bm3, Ws3, bs3,
                                               Wm4, bm4, Ws4, bs4, w16, bias);

    // Layer 1
    alpha1<<<NUMNODES / 32, 256>>>(nodes, Wm1, bm1, att1);
    out1<<<NUMNODES / 32, 256>>>(nodes, Wm1, bm1, Ws1, bs1, xh, xl);

    const dim3 GG(NUMNODES / 64, 9);

    // Layer 2: K=128, C=128
    gemm_mma<128, 128><<<GG, 256, SM128>>>(xh, xl, w16 + 0 * WSLOT,
                                           bias + 0 * 1152, att2, ymsg, yself);
    agg2h<128, 8, true, true, false><<<NUMNODES / 8, 256>>>(ymsg, yself, nullptr, xh, xl);

    // Layer 3: K=128, C=64
    gemm_mma<128, 64><<<GG, 256, SM128>>>(xh, xl, w16 + 1 * WSLOT,
                                          bias + 1 * 1152, att3, ymsg, yself);
    agg2h<64, 16, true, true, false><<<NUMNODES / 16, 256>>>(ymsg, yself, nullptr, xh, xl);

    // Layer 4: K=64, C=64
    gemm_mma<64, 64><<<GG, 256, SM64>>>(xh, xl, w16 + 2 * WSLOT,
                                        bias + 2 * 1152, att4, ymsg, yself);
    agg2h<64, 16, true, false, true><<<NUMNODES / 16, 256>>>(ymsg, yself, bufB, nullptr, nullptr);

    // Layer 5 (small, fp32) — reuse yself as stride-64 scratch
    msg5<<<NUMNODES / 8, 256>>>(bufB, Wm5, bm5, Ws5, bs5, att5, yself);
    agg5<<<NUMNODES / 32, 256>>>(yself, bufA);

    final_k<<<1, 1024>>>(bufA, Wc, bc, (float*)d_out, out_size);
}